// round 1
// baseline (speedup 1.0000x reference)
#include <cuda_runtime.h>
#include <math.h>

// Problem constants
#define Pn   2000
#define Mn   150
#define DGn  2000
#define Fn   256
#define Hn   4
#define DHn  64
#define N1n  2150   // P + M
#define N2n  4000   // P + DG
#define E1n  137600
#define E2n  256000
#define EGPn 64000
#define EGMn 4800

// Output layout (flattened tuple order)
#define OUT_SIMI 0
#define OUT_DGCN 300000
#define OUT_MED  812000
#define OUT_MGCN 850400
#define OUT_PAT  888800

// ---------------- device scratch (static; no allocations) ----------------
__device__ float g_lat1a[N1n*Fn], g_lat1b[N1n*Fn], g_acc1[N1n*Fn];
__device__ float g_lat2a[N2n*Fn], g_lat2b[N2n*Fn], g_acc2[N2n*Fn];
__device__ int   g_cnt[N2n];
__device__ int   g_offs1[N1n+1], g_cur1[N1n+1];
__device__ int   g_offs2[N2n+1], g_cur2[N2n+1];
__device__ int   g_scol1[E1n];  __device__ float g_sval1[E1n];
__device__ int   g_scol2[E2n];  __device__ float g_sval2[E2n];
__device__ int   g_offsg0[Pn+1], g_curg0[Pn+1]; __device__ int g_ssrc0[EGPn];
__device__ int   g_offsg1[Pn+1], g_curg1[Pn+1]; __device__ int g_ssrc1[EGPn];
__device__ int   g_offsg2[Mn+1], g_curg2[Mn+1]; __device__ int g_ssrc2[EGMn];
__device__ int   g_offsg3[Mn+1], g_curg3[Mn+1]; __device__ int g_ssrc3[EGMn];
__device__ float g_feat[Pn*Fn];
__device__ float g_el[Pn*Hn], g_er[Pn*Hn];
__device__ float g_e0[Pn*Fn], g_e1[Pn*Fn], g_e2[Mn*Fn], g_e3[Mn*Fn];
__device__ float g_wsum[4];
__device__ float g_tvec[Mn];

// ---------------- small utility kernels ----------------
__global__ void k_zero_i(int* p, int n){
    int i = blockIdx.x*blockDim.x + threadIdx.x;
    if (i < n) p[i] = 0;
}
__global__ void k_zero_f(float* p, int n){
    int i = blockIdx.x*blockDim.x + threadIdx.x;
    if (i < n) p[i] = 0.f;
}
__global__ void k_copy(const float* __restrict__ s, float* __restrict__ d, int n){
    int i = blockIdx.x*blockDim.x + threadIdx.x;
    if (i < n) d[i] = s[i];
}
__global__ void k_hist(const int* __restrict__ keys, int n, int* cnt){
    int i = blockIdx.x*blockDim.x + threadIdx.x;
    if (i < n) atomicAdd(&cnt[keys[i]], 1);
}
// Exclusive scan over n <= 4096 counters (one block of 1024 threads).
__global__ void k_exscan(const int* __restrict__ cnt, int n, int* offs, int* cur){
    __shared__ int sh[1024];
    int t = threadIdx.x;
    int base = t*4;
    int v[4]; int s = 0;
    #pragma unroll
    for (int i = 0; i < 4; i++){
        v[i] = s;
        int x = (base+i < n) ? cnt[base+i] : 0;
        s += x;
    }
    sh[t] = s; __syncthreads();
    for (int off = 1; off < 1024; off <<= 1){
        int x = 0;
        if (t >= off) x = sh[t-off];
        __syncthreads();
        sh[t] += x;
        __syncthreads();
    }
    int prev = (t == 0) ? 0 : sh[t-1];
    #pragma unroll
    for (int i = 0; i < 4; i++){
        if (base+i < n){
            int o = prev + v[i];
            offs[base+i] = o;
            cur[base+i]  = o;
        }
    }
    if (t == 1023) offs[n] = sh[1023];
}
__global__ void k_scatter_spmm(const int* __restrict__ rows, const int* __restrict__ cols,
                               const float* __restrict__ vals, int n, int* cur,
                               int* __restrict__ scol, float* __restrict__ sval){
    int i = blockIdx.x*blockDim.x + threadIdx.x;
    if (i < n){
        int pos = atomicAdd(&cur[rows[i]], 1);
        scol[pos] = cols[i];
        sval[pos] = vals[i];
    }
}
__global__ void k_scatter_gat(const int* __restrict__ dst, const int* __restrict__ src,
                              int n, int* cur, int* __restrict__ ssrc){
    int i = blockIdx.x*blockDim.x + threadIdx.x;
    if (i < n){
        int pos = atomicAdd(&cur[dst[i]], 1);
        ssrc[pos] = src[i];
    }
}

// init: lat = concat(embA, embB); acc = 0
__global__ void k_init_cat(const float* __restrict__ embA, int nA_elems,
                           const float* __restrict__ embB,
                           float* __restrict__ lat, float* __restrict__ acc, int total){
    int i = blockIdx.x*blockDim.x + threadIdx.x;
    if (i < total){
        lat[i] = (i < nA_elems) ? embA[i] : embB[i - nA_elems];
        acc[i] = 0.f;
    }
}

// ---------------- SpMM: warp per row, gather, fused leaky_relu(0.5) + acc ----------------
__global__ void k_spmm(const int* __restrict__ offs, const int* __restrict__ scol,
                       const float* __restrict__ sval, const float* __restrict__ x,
                       float* __restrict__ lat_out, float* __restrict__ acc, int nrows){
    int w = (blockIdx.x*blockDim.x + threadIdx.x) >> 5;
    int lane = threadIdx.x & 31;
    if (w >= nrows) return;
    int beg = offs[w], end = offs[w+1];
    float4 a0 = make_float4(0.f,0.f,0.f,0.f);
    float4 a1 = make_float4(0.f,0.f,0.f,0.f);
    for (int base = beg; base < end; base += 32){
        int e = base + lane;
        int c = 0; float v = 0.f;
        if (e < end){ c = scol[e]; v = sval[e]; }
        int cnt = min(32, end - base);
        if (cnt == 32){
            #pragma unroll 8
            for (int k = 0; k < 32; k++){
                int cc = __shfl_sync(0xffffffffu, c, k);
                float vv = __shfl_sync(0xffffffffu, v, k);
                const float4* xr = (const float4*)(x + (size_t)cc * Fn);
                float4 b0 = xr[lane], b1 = xr[lane+32];
                a0.x = fmaf(vv,b0.x,a0.x); a0.y = fmaf(vv,b0.y,a0.y);
                a0.z = fmaf(vv,b0.z,a0.z); a0.w = fmaf(vv,b0.w,a0.w);
                a1.x = fmaf(vv,b1.x,a1.x); a1.y = fmaf(vv,b1.y,a1.y);
                a1.z = fmaf(vv,b1.z,a1.z); a1.w = fmaf(vv,b1.w,a1.w);
            }
        } else {
            for (int k = 0; k < cnt; k++){
                int cc = __shfl_sync(0xffffffffu, c, k);
                float vv = __shfl_sync(0xffffffffu, v, k);
                const float4* xr = (const float4*)(x + (size_t)cc * Fn);
                float4 b0 = xr[lane], b1 = xr[lane+32];
                a0.x = fmaf(vv,b0.x,a0.x); a0.y = fmaf(vv,b0.y,a0.y);
                a0.z = fmaf(vv,b0.z,a0.z); a0.w = fmaf(vv,b0.w,a0.w);
                a1.x = fmaf(vv,b1.x,a1.x); a1.y = fmaf(vv,b1.y,a1.y);
                a1.z = fmaf(vv,b1.z,a1.z); a1.w = fmaf(vv,b1.w,a1.w);
            }
        }
    }
    // leaky relu slope 0.5
    a0.x = a0.x > 0.f ? a0.x : 0.5f*a0.x;  a0.y = a0.y > 0.f ? a0.y : 0.5f*a0.y;
    a0.z = a0.z > 0.f ? a0.z : 0.5f*a0.z;  a0.w = a0.w > 0.f ? a0.w : 0.5f*a0.w;
    a1.x = a1.x > 0.f ? a1.x : 0.5f*a1.x;  a1.y = a1.y > 0.f ? a1.y : 0.5f*a1.y;
    a1.z = a1.z > 0.f ? a1.z : 0.5f*a1.z;  a1.w = a1.w > 0.f ? a1.w : 0.5f*a1.w;
    float4* lo = (float4*)(lat_out + (size_t)w * Fn);
    float4* ac = (float4*)(acc     + (size_t)w * Fn);
    float4 p0 = ac[lane];    p0.x += a0.x; p0.y += a0.y; p0.z += a0.z; p0.w += a0.w; ac[lane]    = p0;
    float4 p1 = ac[lane+32]; p1.x += a1.x; p1.y += a1.y; p1.z += a1.z; p1.w += a1.w; ac[lane+32] = p1;
    lo[lane] = a0; lo[lane+32] = a1;
}

// ---------------- GEMM: C[n,256] = A[n,256] @ W[256,256] ----------------
__global__ void k_gemm256(const float* __restrict__ A, const float* __restrict__ W,
                          float* __restrict__ C, int n){
    __shared__ float sA[256][16];   // transposed tile: sA[k][r]
    int r0 = blockIdx.x * 16;
    for (int i = threadIdx.x; i < 16*256; i += 256){
        int r = i >> 8, k = i & 255;
        sA[k][r] = (r0 + r < n) ? A[(size_t)(r0+r)*256 + k] : 0.f;
    }
    __syncthreads();
    int c = threadIdx.x;
    float acc[16];
    #pragma unroll
    for (int r = 0; r < 16; r++) acc[r] = 0.f;
    for (int k = 0; k < 256; k++){
        float wv = W[k*256 + c];
        const float4* s4 = (const float4*)sA[k];
        #pragma unroll
        for (int r4 = 0; r4 < 4; r4++){
            float4 av = s4[r4];
            acc[4*r4+0] = fmaf(av.x, wv, acc[4*r4+0]);
            acc[4*r4+1] = fmaf(av.y, wv, acc[4*r4+1]);
            acc[4*r4+2] = fmaf(av.z, wv, acc[4*r4+2]);
            acc[4*r4+3] = fmaf(av.w, wv, acc[4*r4+3]);
        }
    }
    #pragma unroll
    for (int r = 0; r < 16; r++)
        if (r0 + r < n) C[(size_t)(r0+r)*256 + c] = acc[r];
}

// ---------------- el/er: warp per node ----------------
__global__ void k_elr(const float* __restrict__ feat, const float* __restrict__ al,
                      const float* __restrict__ ar, float* __restrict__ el,
                      float* __restrict__ er, int n){
    int w = (blockIdx.x*blockDim.x + threadIdx.x) >> 5;
    int lane = threadIdx.x & 31;
    if (w >= n) return;
    const float4* fr = (const float4*)(feat + (size_t)w * Fn);
    const float4* a4 = (const float4*)al;
    const float4* r4 = (const float4*)ar;
    float4 f0 = fr[2*lane], f1 = fr[2*lane+1];
    float4 A0 = a4[2*lane], A1 = a4[2*lane+1];
    float4 R0 = r4[2*lane], R1 = r4[2*lane+1];
    float sl = f0.x*A0.x + f0.y*A0.y + f0.z*A0.z + f0.w*A0.w
             + f1.x*A1.x + f1.y*A1.y + f1.z*A1.z + f1.w*A1.w;
    float sr = f0.x*R0.x + f0.y*R0.y + f0.z*R0.z + f0.w*R0.w
             + f1.x*R1.x + f1.y*R1.y + f1.z*R1.z + f1.w*R1.w;
    for (int o = 4; o >= 1; o >>= 1){
        sl += __shfl_down_sync(0xffffffffu, sl, o, 8);
        sr += __shfl_down_sync(0xffffffffu, sr, o, 8);
    }
    if ((lane & 7) == 0){
        el[w*4 + (lane>>3)] = sl;
        er[w*4 + (lane>>3)] = sr;
    }
}

// ---------------- GAT segment softmax + aggregate: warp per dst node ----------------
__device__ __forceinline__ float lrelu2(float x){ return x > 0.f ? x : 0.2f*x; }

__global__ void k_gat(const int* __restrict__ offs, const int* __restrict__ ssrc,
                      const float* __restrict__ el, const float* __restrict__ er,
                      const float* __restrict__ feat, const float* __restrict__ bias,
                      float* __restrict__ out, int n){
    int w = (blockIdx.x*blockDim.x + threadIdx.x) >> 5;
    int lane = threadIdx.x & 31;
    if (w >= n) return;
    int beg = offs[w], end = offs[w+1];
    float4 erv = *(const float4*)(er + w*4);

    // pass 1: per-head max
    float m0 = -1e30f, m1 = -1e30f, m2 = -1e30f, m3 = -1e30f;
    for (int e = beg + lane; e < end; e += 32){
        int s = ssrc[e];
        float4 elv = *(const float4*)(el + s*4);
        m0 = fmaxf(m0, lrelu2(elv.x + erv.x));
        m1 = fmaxf(m1, lrelu2(elv.y + erv.y));
        m2 = fmaxf(m2, lrelu2(elv.z + erv.z));
        m3 = fmaxf(m3, lrelu2(elv.w + erv.w));
    }
    for (int o = 16; o >= 1; o >>= 1){
        m0 = fmaxf(m0, __shfl_xor_sync(0xffffffffu, m0, o));
        m1 = fmaxf(m1, __shfl_xor_sync(0xffffffffu, m1, o));
        m2 = fmaxf(m2, __shfl_xor_sync(0xffffffffu, m2, o));
        m3 = fmaxf(m3, __shfl_xor_sync(0xffffffffu, m3, o));
    }
    // pass 2: per-head sum of exp
    float s0 = 0.f, s1 = 0.f, s2 = 0.f, s3 = 0.f;
    for (int e = beg + lane; e < end; e += 32){
        int s = ssrc[e];
        float4 elv = *(const float4*)(el + s*4);
        s0 += expf(lrelu2(elv.x + erv.x) - m0);
        s1 += expf(lrelu2(elv.y + erv.y) - m1);
        s2 += expf(lrelu2(elv.z + erv.z) - m2);
        s3 += expf(lrelu2(elv.w + erv.w) - m3);
    }
    for (int o = 16; o >= 1; o >>= 1){
        s0 += __shfl_xor_sync(0xffffffffu, s0, o);
        s1 += __shfl_xor_sync(0xffffffffu, s1, o);
        s2 += __shfl_xor_sync(0xffffffffu, s2, o);
        s3 += __shfl_xor_sync(0xffffffffu, s3, o);
    }
    float d0 = 1.f/(s0 + 1e-9f), d1 = 1.f/(s1 + 1e-9f);
    float d2 = 1.f/(s2 + 1e-9f), d3 = 1.f/(s3 + 1e-9f);

    // pass 3: weighted aggregation. Alphas computed once per edge (staging lane),
    // broadcast via shfl; lane selects the head pair matching its feature columns.
    float4 a0 = make_float4(0.f,0.f,0.f,0.f);
    float4 a1 = make_float4(0.f,0.f,0.f,0.f);
    bool lo16 = (lane < 16);
    for (int base = beg; base < end; base += 32){
        int e = base + lane;
        int sidx = 0; float p0 = 0.f, p1 = 0.f, p2 = 0.f, p3 = 0.f;
        if (e < end){
            sidx = ssrc[e];
            float4 elv = *(const float4*)(el + sidx*4);
            p0 = expf(lrelu2(elv.x + erv.x) - m0) * d0;
            p1 = expf(lrelu2(elv.y + erv.y) - m1) * d1;
            p2 = expf(lrelu2(elv.z + erv.z) - m2) * d2;
            p3 = expf(lrelu2(elv.w + erv.w) - m3) * d3;
        }
        int cnt = min(32, end - base);
        for (int k = 0; k < cnt; k++){
            int ss = __shfl_sync(0xffffffffu, sidx, k);
            float q0 = __shfl_sync(0xffffffffu, p0, k);
            float q1 = __shfl_sync(0xffffffffu, p1, k);
            float q2 = __shfl_sync(0xffffffffu, p2, k);
            float q3 = __shfl_sync(0xffffffffu, p3, k);
            float w0 = lo16 ? q0 : q1;   // cols [0,128): heads 0/1
            float w1 = lo16 ? q2 : q3;   // cols [128,256): heads 2/3
            const float4* fr = (const float4*)(feat + (size_t)ss * Fn);
            float4 f0 = fr[lane], f1 = fr[lane+32];
            a0.x = fmaf(w0,f0.x,a0.x); a0.y = fmaf(w0,f0.y,a0.y);
            a0.z = fmaf(w0,f0.z,a0.z); a0.w = fmaf(w0,f0.w,a0.w);
            a1.x = fmaf(w1,f1.x,a1.x); a1.y = fmaf(w1,f1.y,a1.y);
            a1.z = fmaf(w1,f1.z,a1.z); a1.w = fmaf(w1,f1.w,a1.w);
        }
    }
    const float4* b4 = (const float4*)bias;
    float4 bb0 = b4[lane], bb1 = b4[lane+32];
    a0.x += bb0.x; a0.y += bb0.y; a0.z += bb0.z; a0.w += bb0.w;
    a1.x += bb1.x; a1.y += bb1.y; a1.z += bb1.z; a1.w += bb1.w;
    // ELU
    a0.x = a0.x > 0.f ? a0.x : expm1f(a0.x);  a0.y = a0.y > 0.f ? a0.y : expm1f(a0.y);
    a0.z = a0.z > 0.f ? a0.z : expm1f(a0.z);  a0.w = a0.w > 0.f ? a0.w : expm1f(a0.w);
    a1.x = a1.x > 0.f ? a1.x : expm1f(a1.x);  a1.y = a1.y > 0.f ? a1.y : expm1f(a1.y);
    a1.z = a1.z > 0.f ? a1.z : expm1f(a1.z);  a1.w = a1.w > 0.f ? a1.w : expm1f(a1.w);
    float4* o4 = (float4*)(out + (size_t)w * Fn);
    o4[lane] = a0; o4[lane+32] = a1;
}

// ---------------- semantic attention: per-node score, block per node ----------------
__global__ void k_semw(const float* __restrict__ z, const float* __restrict__ W1,
                       const float* __restrict__ b1, const float* __restrict__ W2,
                       float* wslot){
    __shared__ float se[256];
    __shared__ float red[128];
    int node = blockIdx.x;
    int t = threadIdx.x;   // 128 threads
    se[t]       = z[(size_t)node*256 + t];
    se[t + 128] = z[(size_t)node*256 + t + 128];
    __syncthreads();
    float s = b1[t];
    for (int k = 0; k < 256; k++) s = fmaf(se[k], W1[k*128 + t], s);
    red[t] = tanhf(s) * W2[t];
    __syncthreads();
    for (int o = 64; o >= 1; o >>= 1){
        if (t < o) red[t] += red[t + o];
        __syncthreads();
    }
    if (t == 0) atomicAdd(wslot, red[0]);
}

__global__ void k_combine(const float* __restrict__ z0, const float* __restrict__ z1,
                          const float* __restrict__ ws, float invn,
                          float* __restrict__ out, int total){
    int i = blockIdx.x*blockDim.x + threadIdx.x;
    if (i >= total) return;
    float w0 = ws[0]*invn, w1 = ws[1]*invn;
    float m = fmaxf(w0, w1);
    float e0 = expf(w0 - m), e1 = expf(w1 - m);
    float inv = 1.f/(e0 + e1);
    out[i] = (e0*inv)*z0[i] + (e1*inv)*z1[i];
}

// ---------------- final: t[j] = (sum_i relu(med_i)) . W_bot[:,j] ----------------
__global__ void k_medt(const float* __restrict__ med, const float* __restrict__ outW,
                       float* __restrict__ tvec){
    __shared__ float ms[256];
    int t = threadIdx.x;  // 256
    float s = 0.f;
    for (int i = 0; i < Mn; i++) s += fmaxf(med[i*256 + t], 0.f);
    ms[t] = s; __syncthreads();
    if (t < Mn){
        float acc = 0.f;
        for (int k = 0; k < 256; k++) acc = fmaf(ms[k], outW[(256 + k)*Mn + t], acc);
        tvec[t] = acc;
    }
}

// simi_pm[p,j] = M*( relu(patient[p]) . W_top[:,j] + b[j] ) + t[j]
__global__ void k_final(const float* __restrict__ patient, const float* __restrict__ outW,
                        const float* __restrict__ outb, const float* __restrict__ tvec,
                        float* __restrict__ simi){
    __shared__ float sA[256][8];
    int r0 = blockIdx.x * 8;
    for (int i = threadIdx.x; i < 8*256; i += blockDim.x){
        int r = i >> 8, k = i & 255;
        float v = (r0 + r < Pn) ? patient[(size_t)(r0+r)*256 + k] : 0.f;
        sA[k][r] = fmaxf(v, 0.f);
    }
    __syncthreads();
    int j = threadIdx.x;
    if (j < Mn){
        float acc[8];
        #pragma unroll
        for (int r = 0; r < 8; r++) acc[r] = 0.f;
        for (int k = 0; k < 256; k++){
            float wv = outW[k*Mn + j];
            const float4 a40 = *(const float4*)&sA[k][0];
            const float4 a41 = *(const float4*)&sA[k][4];
            acc[0] = fmaf(a40.x, wv, acc[0]); acc[1] = fmaf(a40.y, wv, acc[1]);
            acc[2] = fmaf(a40.z, wv, acc[2]); acc[3] = fmaf(a40.w, wv, acc[3]);
            acc[4] = fmaf(a41.x, wv, acc[4]); acc[5] = fmaf(a41.y, wv, acc[5]);
            acc[6] = fmaf(a41.z, wv, acc[6]); acc[7] = fmaf(a41.w, wv, acc[7]);
        }
        float tv = tvec[j], bb = outb[j];
        #pragma unroll
        for (int r = 0; r < 8; r++)
            if (r0 + r < Pn)
                simi[(size_t)(r0+r)*Mn + j] = (float)Mn * (acc[r] + bb) + tv;
    }
}

// ---------------- host launch ----------------
template <typename T>
static T* symaddr(const void* sym){
    void* p = nullptr;
    cudaGetSymbolAddress(&p, sym);
    return (T*)p;
}

extern "C" void kernel_launch(void* const* d_in, const int* in_sizes, int n_in,
                              void* d_out, int out_size){
    const int*   a1r = (const int*)  d_in[0];
    const int*   a1c = (const int*)  d_in[1];
    const float* a1v = (const float*)d_in[2];
    const int*   a2r = (const int*)  d_in[3];
    const int*   a2c = (const int*)  d_in[4];
    const float* a2v = (const float*)d_in[5];
    const int*   g0s = (const int*)  d_in[6];
    const int*   g0d = (const int*)  d_in[7];
    const int*   g1s = (const int*)  d_in[8];
    const int*   g1d = (const int*)  d_in[9];
    const int*   g2s = (const int*)  d_in[10];
    const int*   g2d = (const int*)  d_in[11];
    const int*   g3s = (const int*)  d_in[12];
    const int*   g3d = (const int*)  d_in[13];
    // keepRate may or may not be surfaced as an input; detect via input count.
    int kr = (n_in >= 27) ? 1 : 0;
    const float* pE    = (const float*)d_in[14 + kr];
    const float* mE    = (const float*)d_in[15 + kr];
    const float* dE    = (const float*)d_in[16 + kr];
    const float* gatW  = (const float*)d_in[17 + kr];
    const float* gatAl = (const float*)d_in[18 + kr];
    const float* gatAr = (const float*)d_in[19 + kr];
    const float* gatB  = (const float*)d_in[20 + kr];
    const float* saW1  = (const float*)d_in[21 + kr];
    const float* saB1  = (const float*)d_in[22 + kr];
    const float* saW2  = (const float*)d_in[23 + kr];
    const float* outW  = (const float*)d_in[24 + kr];
    const float* outB  = (const float*)d_in[25 + kr];
    float* out = (float*)d_out;

    float* lat1a = symaddr<float>(g_lat1a); float* lat1b = symaddr<float>(g_lat1b);
    float* acc1  = symaddr<float>(g_acc1);
    float* lat2a = symaddr<float>(g_lat2a); float* lat2b = symaddr<float>(g_lat2b);
    float* acc2  = symaddr<float>(g_acc2);
    int* cnt   = symaddr<int>(g_cnt);
    int* offs1 = symaddr<int>(g_offs1); int* cur1 = symaddr<int>(g_cur1);
    int* offs2 = symaddr<int>(g_offs2); int* cur2 = symaddr<int>(g_cur2);
    int* scol1 = symaddr<int>(g_scol1); float* sval1 = symaddr<float>(g_sval1);
    int* scol2 = symaddr<int>(g_scol2); float* sval2 = symaddr<float>(g_sval2);
    int* offsg0 = symaddr<int>(g_offsg0); int* curg0 = symaddr<int>(g_curg0); int* ssrc0 = symaddr<int>(g_ssrc0);
    int* offsg1 = symaddr<int>(g_offsg1); int* curg1 = symaddr<int>(g_curg1); int* ssrc1 = symaddr<int>(g_ssrc1);
    int* offsg2 = symaddr<int>(g_offsg2); int* curg2 = symaddr<int>(g_curg2); int* ssrc2 = symaddr<int>(g_ssrc2);
    int* offsg3 = symaddr<int>(g_offsg3); int* curg3 = symaddr<int>(g_curg3); int* ssrc3 = symaddr<int>(g_ssrc3);
    float* feat = symaddr<float>(g_feat);
    float* el = symaddr<float>(g_el); float* er = symaddr<float>(g_er);
    float* e0 = symaddr<float>(g_e0); float* e1 = symaddr<float>(g_e1);
    float* e2 = symaddr<float>(g_e2); float* e3 = symaddr<float>(g_e3);
    float* wsum = symaddr<float>(g_wsum);
    float* tvec = symaddr<float>(g_tvec);

    const int B = 256;
    // ---- CSR builds (reuse cnt buffer; sequential in stream) ----
    // adj1 by row
    k_zero_i<<<(N1n+B-1)/B, B>>>(cnt, N1n);
    k_hist<<<(E1n+B-1)/B, B>>>(a1r, E1n, cnt);
    k_exscan<<<1, 1024>>>(cnt, N1n, offs1, cur1);
    k_scatter_spmm<<<(E1n+B-1)/B, B>>>(a1r, a1c, a1v, E1n, cur1, scol1, sval1);
    // adj2 by row
    k_zero_i<<<(N2n+B-1)/B, B>>>(cnt, N2n);
    k_hist<<<(E2n+B-1)/B, B>>>(a2r, E2n, cnt);
    k_exscan<<<1, 1024>>>(cnt, N2n, offs2, cur2);
    k_scatter_spmm<<<(E2n+B-1)/B, B>>>(a2r, a2c, a2v, E2n, cur2, scol2, sval2);
    // g0..g3 by dst
    k_zero_i<<<(Pn+B-1)/B, B>>>(cnt, Pn);
    k_hist<<<(EGPn+B-1)/B, B>>>(g0d, EGPn, cnt);
    k_exscan<<<1, 1024>>>(cnt, Pn, offsg0, curg0);
    k_scatter_gat<<<(EGPn+B-1)/B, B>>>(g0d, g0s, EGPn, curg0, ssrc0);

    k_zero_i<<<(Pn+B-1)/B, B>>>(cnt, Pn);
    k_hist<<<(EGPn+B-1)/B, B>>>(g1d, EGPn, cnt);
    k_exscan<<<1, 1024>>>(cnt, Pn, offsg1, curg1);
    k_scatter_gat<<<(EGPn+B-1)/B, B>>>(g1d, g1s, EGPn, curg1, ssrc1);

    k_zero_i<<<(Mn+B-1)/B, B>>>(cnt, Mn);
    k_hist<<<(EGMn+B-1)/B, B>>>(g2d, EGMn, cnt);
    k_exscan<<<1, 1024>>>(cnt, Mn, offsg2, curg2);
    k_scatter_gat<<<(EGMn+B-1)/B, B>>>(g2d, g2s, EGMn, curg2, ssrc2);

    k_zero_i<<<(Mn+B-1)/B, B>>>(cnt, Mn);
    k_hist<<<(EGMn+B-1)/B, B>>>(g3d, EGMn, cnt);
    k_exscan<<<1, 1024>>>(cnt, Mn, offsg3, curg3);
    k_scatter_gat<<<(EGMn+B-1)/B, B>>>(g3d, g3s, EGMn, curg3, ssrc3);

    // ---- init embeds + zero acc ----
    k_init_cat<<<(N1n*Fn+B-1)/B, B>>>(pE, Pn*Fn, mE, lat1a, acc1, N1n*Fn);
    k_init_cat<<<(N2n*Fn+B-1)/B, B>>>(pE, Pn*Fn, dE, lat2a, acc2, N2n*Fn);

    // ---- 2 GNN layers ----
    k_spmm<<<(N1n+7)/8, B>>>(offs1, scol1, sval1, lat1a, lat1b, acc1, N1n);
    k_spmm<<<(N2n+7)/8, B>>>(offs2, scol2, sval2, lat2a, lat2b, acc2, N2n);
    k_spmm<<<(N1n+7)/8, B>>>(offs1, scol1, sval1, lat1b, lat1a, acc1, N1n);
    k_spmm<<<(N2n+7)/8, B>>>(offs2, scol2, sval2, lat2b, lat2a, acc2, N2n);

    const float* p1    = acc1;             // acc1[:P]
    const float* mgcn  = acc1 + (size_t)Pn*Fn;
    const float* p2    = acc2;             // acc2[:P]
    const float* dgcn  = acc2 + (size_t)Pn*Fn;

    // ---- 4 GATs ----
    // GAT0: p1, g0
    k_gemm256<<<(Pn+15)/16, 256>>>(p1, gatW + 0*Fn*Fn, feat, Pn);
    k_elr<<<(Pn+7)/8, B>>>(feat, gatAl + 0*256, gatAr + 0*256, el, er, Pn);
    k_gat<<<(Pn+7)/8, B>>>(offsg0, ssrc0, el, er, feat, gatB + 0*256, e0, Pn);
    // GAT1: p2, g1
    k_gemm256<<<(Pn+15)/16, 256>>>(p2, gatW + 1*Fn*Fn, feat, Pn);
    k_elr<<<(Pn+7)/8, B>>>(feat, gatAl + 1*256, gatAr + 1*256, el, er, Pn);
    k_gat<<<(Pn+7)/8, B>>>(offsg1, ssrc1, el, er, feat, gatB + 1*256, e1, Pn);
    // GAT2: m_gcn, g2
    k_gemm256<<<(Mn+15)/16, 256>>>(mgcn, gatW + 2*Fn*Fn, feat, Mn);
    k_elr<<<(Mn+7)/8, B>>>(feat, gatAl + 2*256, gatAr + 2*256, el, er, Mn);
    k_gat<<<(Mn+7)/8, B>>>(offsg2, ssrc2, el, er, feat, gatB + 2*256, e2, Mn);
    // GAT3: m_gcn, g3
    k_gemm256<<<(Mn+15)/16, 256>>>(mgcn, gatW + 3*Fn*Fn, feat, Mn);
    k_elr<<<(Mn+7)/8, B>>>(feat, gatAl + 3*256, gatAr + 3*256, el, er, Mn);
    k_gat<<<(Mn+7)/8, B>>>(offsg3, ssrc3, el, er, feat, gatB + 3*256, e3, Mn);

    // ---- semantic attention ----
    k_zero_f<<<1, 32>>>(wsum, 4);
    k_semw<<<Pn, 128>>>(e0, saW1, saB1, saW2, wsum + 0);
    k_semw<<<Pn, 128>>>(e1, saW1, saB1, saW2, wsum + 1);
    k_semw<<<Mn, 128>>>(e2, saW1, saB1, saW2, wsum + 2);
    k_semw<<<Mn, 128>>>(e3, saW1, saB1, saW2, wsum + 3);
    k_combine<<<(Pn*Fn+B-1)/B, B>>>(e0, e1, wsum + 0, 1.f/(float)Pn, out + OUT_PAT, Pn*Fn);
    k_combine<<<(Mn*Fn+B-1)/B, B>>>(e2, e3, wsum + 2, 1.f/(float)Mn, out + OUT_MED, Mn*Fn);

    // ---- final similarity (algebraically collapsed) ----
    k_medt<<<1, 256>>>(out + OUT_MED, outW, tvec);
    k_final<<<(Pn+7)/8, 160>>>(out + OUT_PAT, outW, outB, tvec, out + OUT_SIMI);

    // ---- remaining raw outputs ----
    k_copy<<<(DGn*Fn+B-1)/B, B>>>(dgcn, out + OUT_DGCN, DGn*Fn);
    k_copy<<<(Mn*Fn+B-1)/B, B>>>(mgcn, out + OUT_MGCN, Mn*Fn);
}

// round 2
// speedup vs baseline: 1.2763x; 1.2763x over previous
#include <cuda_runtime.h>
#include <cuda_fp16.h>
#include <math.h>

// Problem constants
#define Pn   2000
#define Mn   150
#define DGn  2000
#define Fn   256
#define Hn   4
#define DHn  64
#define N1n  2150   // P + M
#define N2n  4000   // P + DG
#define E1n  137600
#define E2n  256000
#define EGPn 64000
#define EGMn 4800
#define ETOT (E1n + E2n + 2*EGPn + 2*EGMn)   // 531200
#define CNT_TOT (N1n + N2n + 2*Pn + 2*Mn)     // 10450

// Output layout (flattened tuple order)
#define OUT_SIMI 0
#define OUT_DGCN 300000
#define OUT_MED  812000
#define OUT_MGCN 850400
#define OUT_PAT  888800

// ---------------- device scratch (static; no allocations) ----------------
__device__ __align__(256) __half g_hlat1a[N1n*Fn], g_hlat1b[N1n*Fn];
__device__ __align__(256) __half g_hlat2a[N2n*Fn], g_hlat2b[N2n*Fn];
__device__ float g_acc1[N1n*Fn];
__device__ float g_acc2[N2n*Fn];
__device__ int   g_cnt[CNT_TOT];
__device__ int   g_offs1[N1n+1], g_cur1[N1n+1];
__device__ int   g_offs2[N2n+1], g_cur2[N2n+1];
__device__ int   g_scol1[E1n];  __device__ float g_sval1[E1n];
__device__ int   g_scol2[E2n];  __device__ float g_sval2[E2n];
__device__ int   g_offsg0[Pn+1], g_curg0[Pn+1]; __device__ int g_ssrc0[EGPn];
__device__ int   g_offsg1[Pn+1], g_curg1[Pn+1]; __device__ int g_ssrc1[EGPn];
__device__ int   g_offsg2[Mn+1], g_curg2[Mn+1]; __device__ int g_ssrc2[EGMn];
__device__ int   g_offsg3[Mn+1], g_curg3[Mn+1]; __device__ int g_ssrc3[EGMn];
__device__ float g_feat[Pn*Fn];
__device__ float g_el[Pn*Hn], g_er[Pn*Hn];
__device__ float g_e0[Pn*Fn], g_e1[Pn*Fn], g_e2[Mn*Fn], g_e3[Mn*Fn];
__device__ float g_wsum[4];
__device__ float g_tvec[Mn];

// ---------------- small utility kernels ----------------
__global__ void k_zero_i(int* p, int n){
    int i = blockIdx.x*blockDim.x + threadIdx.x;
    if (i < n) p[i] = 0;
}
__global__ void k_zero_f(float* p, int n){
    int i = blockIdx.x*blockDim.x + threadIdx.x;
    if (i < n) p[i] = 0.f;
}
__global__ void k_copy(const float* __restrict__ s, float* __restrict__ d, int n){
    int i = blockIdx.x*blockDim.x + threadIdx.x;
    if (i < n) d[i] = s[i];
}

// ---- fused histogram over all six edge lists ----
__global__ void k_hist_all(const int* __restrict__ a1r, const int* __restrict__ a2r,
                           const int* __restrict__ g0d, const int* __restrict__ g1d,
                           const int* __restrict__ g2d, const int* __restrict__ g3d,
                           int* cnt){
    int i = blockIdx.x*blockDim.x + threadIdx.x;
    if (i >= ETOT) return;
    int key, base;
    if (i < E1n){ key = a1r[i]; base = 0; }
    else if (i < E1n+E2n){ key = a2r[i-E1n]; base = N1n; }
    else if (i < E1n+E2n+EGPn){ key = g0d[i-E1n-E2n]; base = N1n+N2n; }
    else if (i < E1n+E2n+2*EGPn){ key = g1d[i-E1n-E2n-EGPn]; base = N1n+N2n+Pn; }
    else if (i < E1n+E2n+2*EGPn+EGMn){ key = g2d[i-E1n-E2n-2*EGPn]; base = N1n+N2n+2*Pn; }
    else { key = g3d[i-E1n-E2n-2*EGPn-EGMn]; base = N1n+N2n+2*Pn+Mn; }
    atomicAdd(&cnt[base + key], 1);
}

// Exclusive scan body for n <= 4096 (one 1024-thread block)
__device__ void exscan_body(const int* __restrict__ cnt, int n, int* offs, int* cur, int* sh){
    int t = threadIdx.x;
    int base = t*4;
    int v[4]; int s = 0;
    #pragma unroll
    for (int i = 0; i < 4; i++){
        v[i] = s;
        int x = (base+i < n) ? cnt[base+i] : 0;
        s += x;
    }
    sh[t] = s; __syncthreads();
    for (int off = 1; off < 1024; off <<= 1){
        int x = 0;
        if (t >= off) x = sh[t-off];
        __syncthreads();
        sh[t] += x;
        __syncthreads();
    }
    int prev = (t == 0) ? 0 : sh[t-1];
    #pragma unroll
    for (int i = 0; i < 4; i++){
        if (base+i < n){
            int o = prev + v[i];
            offs[base+i] = o;
            cur[base+i]  = o;
        }
    }
    if (t == 1023) offs[n] = sh[1023];
}
__global__ void k_exscan_all(const int* __restrict__ cnt,
                             int* o1,int* c1,int* o2,int* c2,
                             int* og0,int* cg0,int* og1,int* cg1,
                             int* og2,int* cg2,int* og3,int* cg3){
    __shared__ int sh[1024];
    switch (blockIdx.x){
        case 0: exscan_body(cnt,               N1n, o1,  c1,  sh); break;
        case 1: exscan_body(cnt+N1n,           N2n, o2,  c2,  sh); break;
        case 2: exscan_body(cnt+N1n+N2n,       Pn,  og0, cg0, sh); break;
        case 3: exscan_body(cnt+N1n+N2n+Pn,    Pn,  og1, cg1, sh); break;
        case 4: exscan_body(cnt+N1n+N2n+2*Pn,  Mn,  og2, cg2, sh); break;
        case 5: exscan_body(cnt+N1n+N2n+2*Pn+Mn, Mn, og3, cg3, sh); break;
    }
}

__global__ void k_scatter_all(const int* __restrict__ a1r, const int* __restrict__ a1c, const float* __restrict__ a1v,
                              const int* __restrict__ a2r, const int* __restrict__ a2c, const float* __restrict__ a2v,
                              const int* __restrict__ g0d, const int* __restrict__ g0s,
                              const int* __restrict__ g1d, const int* __restrict__ g1s,
                              const int* __restrict__ g2d, const int* __restrict__ g2s,
                              const int* __restrict__ g3d, const int* __restrict__ g3s,
                              int* cur1, int* scol1, float* sval1,
                              int* cur2, int* scol2, float* sval2,
                              int* curg0, int* ssrc0, int* curg1, int* ssrc1,
                              int* curg2, int* ssrc2, int* curg3, int* ssrc3){
    int i = blockIdx.x*blockDim.x + threadIdx.x;
    if (i >= ETOT) return;
    if (i < E1n){
        int pos = atomicAdd(&cur1[a1r[i]], 1);
        scol1[pos] = a1c[i]; sval1[pos] = a1v[i];
    } else if (i < E1n+E2n){
        int j = i-E1n;
        int pos = atomicAdd(&cur2[a2r[j]], 1);
        scol2[pos] = a2c[j]; sval2[pos] = a2v[j];
    } else if (i < E1n+E2n+EGPn){
        int j = i-E1n-E2n;
        int pos = atomicAdd(&curg0[g0d[j]], 1);
        ssrc0[pos] = g0s[j];
    } else if (i < E1n+E2n+2*EGPn){
        int j = i-E1n-E2n-EGPn;
        int pos = atomicAdd(&curg1[g1d[j]], 1);
        ssrc1[pos] = g1s[j];
    } else if (i < E1n+E2n+2*EGPn+EGMn){
        int j = i-E1n-E2n-2*EGPn;
        int pos = atomicAdd(&curg2[g2d[j]], 1);
        ssrc2[pos] = g2s[j];
    } else {
        int j = i-E1n-E2n-2*EGPn-EGMn;
        int pos = atomicAdd(&curg3[g3d[j]], 1);
        ssrc3[pos] = g3s[j];
    }
}

// init: lat(half) = concat(embA, embB); acc = 0
__global__ void k_init_cat_h(const float* __restrict__ embA, int nA_elems,
                             const float* __restrict__ embB,
                             __half* __restrict__ lat, float* __restrict__ acc, int total){
    int i = blockIdx.x*blockDim.x + threadIdx.x;
    if (i < total){
        float v = (i < nA_elems) ? embA[i] : embB[i - nA_elems];
        lat[i] = __float2half_rn(v);
        acc[i] = 0.f;
    }
}

// ---------------- SpMM: warp per row, half gather, fp32 accum, fused lrelu + acc ----------------
__global__ void k_spmm_h(const int* __restrict__ offs, const int* __restrict__ scol,
                         const float* __restrict__ sval, const __half* __restrict__ x,
                         __half* __restrict__ lat_out, float* __restrict__ acc, int nrows){
    int w = (blockIdx.x*blockDim.x + threadIdx.x) >> 5;
    int lane = threadIdx.x & 31;
    if (w >= nrows) return;
    int beg = offs[w], end = offs[w+1];
    float a0=0.f,a1=0.f,a2=0.f,a3=0.f,a4=0.f,a5=0.f,a6=0.f,a7=0.f;
    for (int base = beg; base < end; base += 32){
        int e = base + lane;
        int c = 0; float v = 0.f;
        if (e < end){ c = scol[e]; v = sval[e]; }
        int cnt = min(32, end - base);
        #pragma unroll 4
        for (int k = 0; k < cnt; k++){
            int cc = __shfl_sync(0xffffffffu, c, k);
            float vv = __shfl_sync(0xffffffffu, v, k);
            float4 raw = ((const float4*)(x + (size_t)cc * Fn))[lane];
            const __half2* hp = (const __half2*)&raw;
            float2 f0 = __half22float2(hp[0]);
            float2 f1 = __half22float2(hp[1]);
            float2 f2 = __half22float2(hp[2]);
            float2 f3 = __half22float2(hp[3]);
            a0 = fmaf(vv,f0.x,a0); a1 = fmaf(vv,f0.y,a1);
            a2 = fmaf(vv,f1.x,a2); a3 = fmaf(vv,f1.y,a3);
            a4 = fmaf(vv,f2.x,a4); a5 = fmaf(vv,f2.y,a5);
            a6 = fmaf(vv,f3.x,a6); a7 = fmaf(vv,f3.y,a7);
        }
    }
    // leaky relu slope 0.5
    a0 = a0>0.f?a0:0.5f*a0; a1 = a1>0.f?a1:0.5f*a1;
    a2 = a2>0.f?a2:0.5f*a2; a3 = a3>0.f?a3:0.5f*a3;
    a4 = a4>0.f?a4:0.5f*a4; a5 = a5>0.f?a5:0.5f*a5;
    a6 = a6>0.f?a6:0.5f*a6; a7 = a7>0.f?a7:0.5f*a7;
    // store half lat
    float4 o;
    __half2* op = (__half2*)&o;
    op[0] = __floats2half2_rn(a0,a1);
    op[1] = __floats2half2_rn(a2,a3);
    op[2] = __floats2half2_rn(a4,a5);
    op[3] = __floats2half2_rn(a6,a7);
    ((float4*)(lat_out + (size_t)w * Fn))[lane] = o;
    // fp32 acc
    float4* ac = (float4*)(acc + (size_t)w * Fn);
    float4 p0 = ac[2*lane];   p0.x+=a0; p0.y+=a1; p0.z+=a2; p0.w+=a3; ac[2*lane]   = p0;
    float4 p1 = ac[2*lane+1]; p1.x+=a4; p1.y+=a5; p1.z+=a6; p1.w+=a7; ac[2*lane+1] = p1;
}

// ---------------- GEMM: C[n,256] = A[n,256] @ W[256,256] ----------------
__global__ void k_gemm256(const float* __restrict__ A, const float* __restrict__ W,
                          float* __restrict__ C, int n){
    __shared__ float sA[256][16];   // transposed tile: sA[k][r]
    int r0 = blockIdx.x * 16;
    for (int i = threadIdx.x; i < 16*256; i += 256){
        int r = i >> 8, k = i & 255;
        sA[k][r] = (r0 + r < n) ? A[(size_t)(r0+r)*256 + k] : 0.f;
    }
    __syncthreads();
    int c = threadIdx.x;
    float acc[16];
    #pragma unroll
    for (int r = 0; r < 16; r++) acc[r] = 0.f;
    for (int k = 0; k < 256; k++){
        float wv = W[k*256 + c];
        const float4* s4 = (const float4*)sA[k];
        #pragma unroll
        for (int r4 = 0; r4 < 4; r4++){
            float4 av = s4[r4];
            acc[4*r4+0] = fmaf(av.x, wv, acc[4*r4+0]);
            acc[4*r4+1] = fmaf(av.y, wv, acc[4*r4+1]);
            acc[4*r4+2] = fmaf(av.z, wv, acc[4*r4+2]);
            acc[4*r4+3] = fmaf(av.w, wv, acc[4*r4+3]);
        }
    }
    #pragma unroll
    for (int r = 0; r < 16; r++)
        if (r0 + r < n) C[(size_t)(r0+r)*256 + c] = acc[r];
}

// ---------------- el/er: warp per node ----------------
__global__ void k_elr(const float* __restrict__ feat, const float* __restrict__ al,
                      const float* __restrict__ ar, float* __restrict__ el,
                      float* __restrict__ er, int n){
    int w = (blockIdx.x*blockDim.x + threadIdx.x) >> 5;
    int lane = threadIdx.x & 31;
    if (w >= n) return;
    const float4* fr = (const float4*)(feat + (size_t)w * Fn);
    const float4* a4 = (const float4*)al;
    const float4* r4 = (const float4*)ar;
    float4 f0 = fr[2*lane], f1 = fr[2*lane+1];
    float4 A0 = a4[2*lane], A1 = a4[2*lane+1];
    float4 R0 = r4[2*lane], R1 = r4[2*lane+1];
    float sl = f0.x*A0.x + f0.y*A0.y + f0.z*A0.z + f0.w*A0.w
             + f1.x*A1.x + f1.y*A1.y + f1.z*A1.z + f1.w*A1.w;
    float sr = f0.x*R0.x + f0.y*R0.y + f0.z*R0.z + f0.w*R0.w
             + f1.x*R1.x + f1.y*R1.y + f1.z*R1.z + f1.w*R1.w;
    for (int o = 4; o >= 1; o >>= 1){
        sl += __shfl_down_sync(0xffffffffu, sl, o, 8);
        sr += __shfl_down_sync(0xffffffffu, sr, o, 8);
    }
    if ((lane & 7) == 0){
        el[w*4 + (lane>>3)] = sl;
        er[w*4 + (lane>>3)] = sr;
    }
}

// ---------------- GAT segment softmax + aggregate: warp per dst node ----------------
__device__ __forceinline__ float lrelu2(float x){ return x > 0.f ? x : 0.2f*x; }

__global__ void k_gat(const int* __restrict__ offs, const int* __restrict__ ssrc,
                      const float* __restrict__ el, const float* __restrict__ er,
                      const float* __restrict__ feat, const float* __restrict__ bias,
                      float* __restrict__ out, int n){
    int w = (blockIdx.x*blockDim.x + threadIdx.x) >> 5;
    int lane = threadIdx.x & 31;
    if (w >= n) return;
    int beg = offs[w], end = offs[w+1];
    float4 erv = *(const float4*)(er + w*4);

    float m0 = -1e30f, m1 = -1e30f, m2 = -1e30f, m3 = -1e30f;
    for (int e = beg + lane; e < end; e += 32){
        int s = ssrc[e];
        float4 elv = *(const float4*)(el + s*4);
        m0 = fmaxf(m0, lrelu2(elv.x + erv.x));
        m1 = fmaxf(m1, lrelu2(elv.y + erv.y));
        m2 = fmaxf(m2, lrelu2(elv.z + erv.z));
        m3 = fmaxf(m3, lrelu2(elv.w + erv.w));
    }
    for (int o = 16; o >= 1; o >>= 1){
        m0 = fmaxf(m0, __shfl_xor_sync(0xffffffffu, m0, o));
        m1 = fmaxf(m1, __shfl_xor_sync(0xffffffffu, m1, o));
        m2 = fmaxf(m2, __shfl_xor_sync(0xffffffffu, m2, o));
        m3 = fmaxf(m3, __shfl_xor_sync(0xffffffffu, m3, o));
    }
    float s0 = 0.f, s1 = 0.f, s2 = 0.f, s3 = 0.f;
    for (int e = beg + lane; e < end; e += 32){
        int s = ssrc[e];
        float4 elv = *(const float4*)(el + s*4);
        s0 += expf(lrelu2(elv.x + erv.x) - m0);
        s1 += expf(lrelu2(elv.y + erv.y) - m1);
        s2 += expf(lrelu2(elv.z + erv.z) - m2);
        s3 += expf(lrelu2(elv.w + erv.w) - m3);
    }
    for (int o = 16; o >= 1; o >>= 1){
        s0 += __shfl_xor_sync(0xffffffffu, s0, o);
        s1 += __shfl_xor_sync(0xffffffffu, s1, o);
        s2 += __shfl_xor_sync(0xffffffffu, s2, o);
        s3 += __shfl_xor_sync(0xffffffffu, s3, o);
    }
    float d0 = 1.f/(s0 + 1e-9f), d1 = 1.f/(s1 + 1e-9f);
    float d2 = 1.f/(s2 + 1e-9f), d3 = 1.f/(s3 + 1e-9f);

    float4 a0 = make_float4(0.f,0.f,0.f,0.f);
    float4 a1 = make_float4(0.f,0.f,0.f,0.f);
    bool lo16 = (lane < 16);
    for (int base = beg; base < end; base += 32){
        int e = base + lane;
        int sidx = 0; float p0 = 0.f, p1 = 0.f, p2 = 0.f, p3 = 0.f;
        if (e < end){
            sidx = ssrc[e];
            float4 elv = *(const float4*)(el + sidx*4);
            p0 = expf(lrelu2(elv.x + erv.x) - m0) * d0;
            p1 = expf(lrelu2(elv.y + erv.y) - m1) * d1;
            p2 = expf(lrelu2(elv.z + erv.z) - m2) * d2;
            p3 = expf(lrelu2(elv.w + erv.w) - m3) * d3;
        }
        int cnt = min(32, end - base);
        for (int k = 0; k < cnt; k++){
            int ss = __shfl_sync(0xffffffffu, sidx, k);
            float q0 = __shfl_sync(0xffffffffu, p0, k);
            float q1 = __shfl_sync(0xffffffffu, p1, k);
            float q2 = __shfl_sync(0xffffffffu, p2, k);
            float q3 = __shfl_sync(0xffffffffu, p3, k);
            float w0 = lo16 ? q0 : q1;   // cols [0,128): heads 0/1
            float w1 = lo16 ? q2 : q3;   // cols [128,256): heads 2/3
            const float4* fr = (const float4*)(feat + (size_t)ss * Fn);
            float4 f0 = fr[lane], f1 = fr[lane+32];
            a0.x = fmaf(w0,f0.x,a0.x); a0.y = fmaf(w0,f0.y,a0.y);
            a0.z = fmaf(w0,f0.z,a0.z); a0.w = fmaf(w0,f0.w,a0.w);
            a1.x = fmaf(w1,f1.x,a1.x); a1.y = fmaf(w1,f1.y,a1.y);
            a1.z = fmaf(w1,f1.z,a1.z); a1.w = fmaf(w1,f1.w,a1.w);
        }
    }
    const float4* b4 = (const float4*)bias;
    float4 bb0 = b4[lane], bb1 = b4[lane+32];
    a0.x += bb0.x; a0.y += bb0.y; a0.z += bb0.z; a0.w += bb0.w;
    a1.x += bb1.x; a1.y += bb1.y; a1.z += bb1.z; a1.w += bb1.w;
    a0.x = a0.x > 0.f ? a0.x : expm1f(a0.x);  a0.y = a0.y > 0.f ? a0.y : expm1f(a0.y);
    a0.z = a0.z > 0.f ? a0.z : expm1f(a0.z);  a0.w = a0.w > 0.f ? a0.w : expm1f(a0.w);
    a1.x = a1.x > 0.f ? a1.x : expm1f(a1.x);  a1.y = a1.y > 0.f ? a1.y : expm1f(a1.y);
    a1.z = a1.z > 0.f ? a1.z : expm1f(a1.z);  a1.w = a1.w > 0.f ? a1.w : expm1f(a1.w);
    float4* o4 = (float4*)(out + (size_t)w * Fn);
    o4[lane] = a0; o4[lane+32] = a1;
}

// ---------------- semantic attention scores: tiled GEMM, summed directly ----------------
// wsum[zi] += sum over rows r of tanh(z[r]@W1 + b1) @ W2
__global__ void k_semscore(const float* __restrict__ z0, const float* __restrict__ z1,
                           const float* __restrict__ z2, const float* __restrict__ z3,
                           const float* __restrict__ W1, const float* __restrict__ b1,
                           const float* __restrict__ W2, float* wsum){
    int zi = blockIdx.y;
    const float* z = (zi==0)?z0:(zi==1)?z1:(zi==2)?z2:z3;
    int n = (zi < 2) ? Pn : Mn;
    int r0 = blockIdx.x * 16;
    if (r0 >= n) return;
    __shared__ float sZ[16][256];
    for (int i = threadIdx.x; i < 16*256; i += 128){
        int r = i >> 8, k = i & 255;
        sZ[r][k] = (r0 + r < n) ? z[(size_t)(r0+r)*256 + k] : 0.f;
    }
    __syncthreads();
    int c = threadIdx.x;  // 0..127 hidden unit
    float bc = b1[c];
    float acc[16];
    #pragma unroll
    for (int r = 0; r < 16; r++) acc[r] = bc;
    for (int k = 0; k < 256; k++){
        float w1v = W1[k*128 + c];
        #pragma unroll
        for (int r = 0; r < 16; r++)
            acc[r] = fmaf(sZ[r][k], w1v, acc[r]);
    }
    float w2 = W2[c];
    float local = 0.f;
    #pragma unroll
    for (int r = 0; r < 16; r++)
        if (r0 + r < n) local += tanhf(acc[r]) * w2;
    // block reduce over 128 threads
    for (int o = 16; o >= 1; o >>= 1)
        local += __shfl_xor_sync(0xffffffffu, local, o);
    __shared__ float red[4];
    if ((threadIdx.x & 31) == 0) red[threadIdx.x >> 5] = local;
    __syncthreads();
    if (threadIdx.x == 0)
        atomicAdd(&wsum[zi], red[0] + red[1] + red[2] + red[3]);
}

__global__ void k_combine(const float* __restrict__ z0, const float* __restrict__ z1,
                          const float* __restrict__ ws, float invn,
                          float* __restrict__ out, int total){
    int i = blockIdx.x*blockDim.x + threadIdx.x;
    if (i >= total) return;
    float w0 = ws[0]*invn, w1 = ws[1]*invn;
    float m = fmaxf(w0, w1);
    float e0 = expf(w0 - m), e1 = expf(w1 - m);
    float inv = 1.f/(e0 + e1);
    out[i] = (e0*inv)*z0[i] + (e1*inv)*z1[i];
}

// ---------------- final: t[j] = (sum_i relu(med_i)) . W_bot[:,j] ----------------
__global__ void k_medt(const float* __restrict__ med, const float* __restrict__ outW,
                       float* __restrict__ tvec){
    __shared__ float ms[256];
    int t = threadIdx.x;  // 256
    float s = 0.f;
    for (int i = 0; i < Mn; i++) s += fmaxf(med[i*256 + t], 0.f);
    ms[t] = s; __syncthreads();
    if (t < Mn){
        float acc = 0.f;
        for (int k = 0; k < 256; k++) acc = fmaf(ms[k], outW[(256 + k)*Mn + t], acc);
        tvec[t] = acc;
    }
}

// simi_pm[p,j] = M*( relu(patient[p]) . W_top[:,j] + b[j] ) + t[j]
__global__ void k_final(const float* __restrict__ patient, const float* __restrict__ outW,
                        const float* __restrict__ outb, const float* __restrict__ tvec,
                        float* __restrict__ simi){
    __shared__ float sA[256][8];
    int r0 = blockIdx.x * 8;
    for (int i = threadIdx.x; i < 8*256; i += blockDim.x){
        int r = i >> 8, k = i & 255;
        float v = (r0 + r < Pn) ? patient[(size_t)(r0+r)*256 + k] : 0.f;
        sA[k][r] = fmaxf(v, 0.f);
    }
    __syncthreads();
    int j = threadIdx.x;
    if (j < Mn){
        float acc[8];
        #pragma unroll
        for (int r = 0; r < 8; r++) acc[r] = 0.f;
        for (int k = 0; k < 256; k++){
            float wv = outW[k*Mn + j];
            const float4 a40 = *(const float4*)&sA[k][0];
            const float4 a41 = *(const float4*)&sA[k][4];
            acc[0] = fmaf(a40.x, wv, acc[0]); acc[1] = fmaf(a40.y, wv, acc[1]);
            acc[2] = fmaf(a40.z, wv, acc[2]); acc[3] = fmaf(a40.w, wv, acc[3]);
            acc[4] = fmaf(a41.x, wv, acc[4]); acc[5] = fmaf(a41.y, wv, acc[5]);
            acc[6] = fmaf(a41.z, wv, acc[6]); acc[7] = fmaf(a41.w, wv, acc[7]);
        }
        float tv = tvec[j], bb = outb[j];
        #pragma unroll
        for (int r = 0; r < 8; r++)
            if (r0 + r < Pn)
                simi[(size_t)(r0+r)*Mn + j] = (float)Mn * (acc[r] + bb) + tv;
    }
}

// ---------------- host launch ----------------
template <typename T>
static T* symaddr(const void* sym){
    void* p = nullptr;
    cudaGetSymbolAddress(&p, sym);
    return (T*)p;
}

extern "C" void kernel_launch(void* const* d_in, const int* in_sizes, int n_in,
                              void* d_out, int out_size){
    const int*   a1r = (const int*)  d_in[0];
    const int*   a1c = (const int*)  d_in[1];
    const float* a1v = (const float*)d_in[2];
    const int*   a2r = (const int*)  d_in[3];
    const int*   a2c = (const int*)  d_in[4];
    const float* a2v = (const float*)d_in[5];
    const int*   g0s = (const int*)  d_in[6];
    const int*   g0d = (const int*)  d_in[7];
    const int*   g1s = (const int*)  d_in[8];
    const int*   g1d = (const int*)  d_in[9];
    const int*   g2s = (const int*)  d_in[10];
    const int*   g2d = (const int*)  d_in[11];
    const int*   g3s = (const int*)  d_in[12];
    const int*   g3d = (const int*)  d_in[13];
    int kr = (n_in >= 27) ? 1 : 0;
    const float* pE    = (const float*)d_in[14 + kr];
    const float* mE    = (const float*)d_in[15 + kr];
    const float* dE    = (const float*)d_in[16 + kr];
    const float* gatW  = (const float*)d_in[17 + kr];
    const float* gatAl = (const float*)d_in[18 + kr];
    const float* gatAr = (const float*)d_in[19 + kr];
    const float* gatB  = (const float*)d_in[20 + kr];
    const float* saW1  = (const float*)d_in[21 + kr];
    const float* saB1  = (const float*)d_in[22 + kr];
    const float* saW2  = (const float*)d_in[23 + kr];
    const float* outW  = (const float*)d_in[24 + kr];
    const float* outB  = (const float*)d_in[25 + kr];
    float* out = (float*)d_out;

    __half* hlat1a = symaddr<__half>(g_hlat1a); __half* hlat1b = symaddr<__half>(g_hlat1b);
    __half* hlat2a = symaddr<__half>(g_hlat2a); __half* hlat2b = symaddr<__half>(g_hlat2b);
    float* acc1  = symaddr<float>(g_acc1);
    float* acc2  = symaddr<float>(g_acc2);
    int* cnt   = symaddr<int>(g_cnt);
    int* offs1 = symaddr<int>(g_offs1); int* cur1 = symaddr<int>(g_cur1);
    int* offs2 = symaddr<int>(g_offs2); int* cur2 = symaddr<int>(g_cur2);
    int* scol1 = symaddr<int>(g_scol1); float* sval1 = symaddr<float>(g_sval1);
    int* scol2 = symaddr<int>(g_scol2); float* sval2 = symaddr<float>(g_sval2);
    int* offsg0 = symaddr<int>(g_offsg0); int* curg0 = symaddr<int>(g_curg0); int* ssrc0 = symaddr<int>(g_ssrc0);
    int* offsg1 = symaddr<int>(g_offsg1); int* curg1 = symaddr<int>(g_curg1); int* ssrc1 = symaddr<int>(g_ssrc1);
    int* offsg2 = symaddr<int>(g_offsg2); int* curg2 = symaddr<int>(g_curg2); int* ssrc2 = symaddr<int>(g_ssrc2);
    int* offsg3 = symaddr<int>(g_offsg3); int* curg3 = symaddr<int>(g_curg3); int* ssrc3 = symaddr<int>(g_ssrc3);
    float* feat = symaddr<float>(g_feat);
    float* el = symaddr<float>(g_el); float* er = symaddr<float>(g_er);
    float* e0 = symaddr<float>(g_e0); float* e1 = symaddr<float>(g_e1);
    float* e2 = symaddr<float>(g_e2); float* e3 = symaddr<float>(g_e3);
    float* wsum = symaddr<float>(g_wsum);
    float* tvec = symaddr<float>(g_tvec);

    const int B = 256;

    // ---- fused CSR builds ----
    k_zero_i<<<(CNT_TOT+B-1)/B, B>>>(cnt, CNT_TOT);
    k_zero_f<<<1, 32>>>(wsum, 4);
    k_hist_all<<<(ETOT+B-1)/B, B>>>(a1r, a2r, g0d, g1d, g2d, g3d, cnt);
    k_exscan_all<<<6, 1024>>>(cnt, offs1, cur1, offs2, cur2,
                              offsg0, curg0, offsg1, curg1,
                              offsg2, curg2, offsg3, curg3);
    k_scatter_all<<<(ETOT+B-1)/B, B>>>(a1r, a1c, a1v, a2r, a2c, a2v,
                                       g0d, g0s, g1d, g1s, g2d, g2s, g3d, g3s,
                                       cur1, scol1, sval1, cur2, scol2, sval2,
                                       curg0, ssrc0, curg1, ssrc1,
                                       curg2, ssrc2, curg3, ssrc3);

    // ---- init embeds (half) + zero acc ----
    k_init_cat_h<<<(N1n*Fn+B-1)/B, B>>>(pE, Pn*Fn, mE, hlat1a, acc1, N1n*Fn);
    k_init_cat_h<<<(N2n*Fn+B-1)/B, B>>>(pE, Pn*Fn, dE, hlat2a, acc2, N2n*Fn);

    // ---- 2 GNN layers (half gather, fp32 accum) ----
    k_spmm_h<<<(N1n+7)/8, B>>>(offs1, scol1, sval1, hlat1a, hlat1b, acc1, N1n);
    k_spmm_h<<<(N2n+7)/8, B>>>(offs2, scol2, sval2, hlat2a, hlat2b, acc2, N2n);
    k_spmm_h<<<(N1n+7)/8, B>>>(offs1, scol1, sval1, hlat1b, hlat1a, acc1, N1n);
    k_spmm_h<<<(N2n+7)/8, B>>>(offs2, scol2, sval2, hlat2b, hlat2a, acc2, N2n);

    const float* p1    = acc1;
    const float* mgcn  = acc1 + (size_t)Pn*Fn;
    const float* p2    = acc2;
    const float* dgcn  = acc2 + (size_t)Pn*Fn;

    // ---- 4 GATs ----
    k_gemm256<<<(Pn+15)/16, 256>>>(p1, gatW + 0*Fn*Fn, feat, Pn);
    k_elr<<<(Pn+7)/8, B>>>(feat, gatAl + 0*256, gatAr + 0*256, el, er, Pn);
    k_gat<<<(Pn+7)/8, B>>>(offsg0, ssrc0, el, er, feat, gatB + 0*256, e0, Pn);

    k_gemm256<<<(Pn+15)/16, 256>>>(p2, gatW + 1*Fn*Fn, feat, Pn);
    k_elr<<<(Pn+7)/8, B>>>(feat, gatAl + 1*256, gatAr + 1*256, el, er, Pn);
    k_gat<<<(Pn+7)/8, B>>>(offsg1, ssrc1, el, er, feat, gatB + 1*256, e1, Pn);

    k_gemm256<<<(Mn+15)/16, 256>>>(mgcn, gatW + 2*Fn*Fn, feat, Mn);
    k_elr<<<(Mn+7)/8, B>>>(feat, gatAl + 2*256, gatAr + 2*256, el, er, Mn);
    k_gat<<<(Mn+7)/8, B>>>(offsg2, ssrc2, el, er, feat, gatB + 2*256, e2, Mn);

    k_gemm256<<<(Mn+15)/16, 256>>>(mgcn, gatW + 3*Fn*Fn, feat, Mn);
    k_elr<<<(Mn+7)/8, B>>>(feat, gatAl + 3*256, gatAr + 3*256, el, er, Mn);
    k_gat<<<(Mn+7)/8, B>>>(offsg3, ssrc3, el, er, feat, gatB + 3*256, e3, Mn);

    // ---- semantic attention (tiled GEMM score) ----
    {
        dim3 grid((Pn+15)/16, 4);
        k_semscore<<<grid, 128>>>(e0, e1, e2, e3, saW1, saB1, saW2, wsum);
    }
    k_combine<<<(Pn*Fn+B-1)/B, B>>>(e0, e1, wsum + 0, 1.f/(float)Pn, out + OUT_PAT, Pn*Fn);
    k_combine<<<(Mn*Fn+B-1)/B, B>>>(e2, e3, wsum + 2, 1.f/(float)Mn, out + OUT_MED, Mn*Fn);

    // ---- final similarity (algebraically collapsed) ----
    k_medt<<<1, 256>>>(out + OUT_MED, outW, tvec);
    k_final<<<(Pn+7)/8, 160>>>(out + OUT_PAT, outW, outB, tvec, out + OUT_SIMI);

    // ---- remaining raw outputs ----
    k_copy<<<(DGn*Fn+B-1)/B, B>>>(dgcn, out + OUT_DGCN, DGn*Fn);
    k_copy<<<(Mn*Fn+B-1)/B, B>>>(mgcn, out + OUT_MGCN, Mn*Fn);
}

// round 3
// speedup vs baseline: 1.9193x; 1.5038x over previous
#include <cuda_runtime.h>
#include <cuda_fp16.h>
#include <math.h>

// Problem constants
#define Pn   2000
#define Mn   150
#define DGn  2000
#define Fn   256
#define Hn   4
#define N1n  2150   // P + M
#define N2n  4000   // P + DG
#define E1n  137600
#define E2n  256000
#define EGPn 64000
#define EGMn 4800
#define ETOT (E1n + E2n + 2*EGPn + 2*EGMn)   // 531200
#define CNT_TOT (N1n + N2n + 2*Pn + 2*Mn)     // 10450
#define NGAT (2*Pn + 2*Mn)                    // 4300 total GAT nodes

// Output layout (flattened tuple order)
#define OUT_SIMI 0
#define OUT_DGCN 300000
#define OUT_MED  812000
#define OUT_MGCN 850400
#define OUT_PAT  888800

// ---------------- device scratch (static; no allocations) ----------------
__device__ __align__(256) __half g_hlat1a[N1n*Fn], g_hlat1b[N1n*Fn];
__device__ __align__(256) __half g_hlat2a[N2n*Fn], g_hlat2b[N2n*Fn];
__device__ float g_acc1[N1n*Fn];
__device__ float g_acc2[N2n*Fn];
__device__ int   g_cnt[CNT_TOT];
__device__ int   g_offs1[N1n+1], g_cur1[N1n+1];
__device__ int   g_offs2[N2n+1], g_cur2[N2n+1];
__device__ int   g_scol1[E1n];  __device__ float g_sval1[E1n];
__device__ int   g_scol2[E2n];  __device__ float g_sval2[E2n];
__device__ int   g_offsg0[Pn+1], g_curg0[Pn+1]; __device__ int g_ssrc0[EGPn];
__device__ int   g_offsg1[Pn+1], g_curg1[Pn+1]; __device__ int g_ssrc1[EGPn];
__device__ int   g_offsg2[Mn+1], g_curg2[Mn+1]; __device__ int g_ssrc2[EGMn];
__device__ int   g_offsg3[Mn+1], g_curg3[Mn+1]; __device__ int g_ssrc3[EGMn];
__device__ __align__(256) __half g_feats[NGAT*Fn];   // all 4 GAT feature sets
__device__ float g_el[NGAT*Hn], g_er[NGAT*Hn];
__device__ float g_eall[NGAT*Fn];                    // e0|e1|e2|e3
__device__ float g_wsum[4];
__device__ float g_tvec[Mn];

// node offsets into the concatenated GAT space
#define GOFF0 0
#define GOFF1 Pn
#define GOFF2 (2*Pn)
#define GOFF3 (2*Pn + Mn)

// ---------------- fused zero ----------------
__global__ void k_zero_all(int* cnt, float* wsum){
    int i = blockIdx.x*blockDim.x + threadIdx.x;
    if (i < CNT_TOT) cnt[i] = 0;
    if (i < 4) wsum[i] = 0.f;
}

// ---- fused histogram over all six edge lists ----
__global__ void k_hist_all(const int* __restrict__ a1r, const int* __restrict__ a2r,
                           const int* __restrict__ g0d, const int* __restrict__ g1d,
                           const int* __restrict__ g2d, const int* __restrict__ g3d,
                           int* cnt){
    int i = blockIdx.x*blockDim.x + threadIdx.x;
    if (i >= ETOT) return;
    int key, base;
    if (i < E1n){ key = a1r[i]; base = 0; }
    else if (i < E1n+E2n){ key = a2r[i-E1n]; base = N1n; }
    else if (i < E1n+E2n+EGPn){ key = g0d[i-E1n-E2n]; base = N1n+N2n; }
    else if (i < E1n+E2n+2*EGPn){ key = g1d[i-E1n-E2n-EGPn]; base = N1n+N2n+Pn; }
    else if (i < E1n+E2n+2*EGPn+EGMn){ key = g2d[i-E1n-E2n-2*EGPn]; base = N1n+N2n+2*Pn; }
    else { key = g3d[i-E1n-E2n-2*EGPn-EGMn]; base = N1n+N2n+2*Pn+Mn; }
    atomicAdd(&cnt[base + key], 1);
}

// ---- warp-shuffle exclusive scan, n <= 4096, 1024 threads ----
__device__ void exscan_body(const int* __restrict__ cnt, int n, int* offs, int* cur){
    __shared__ int warpsum[32];
    int t = threadIdx.x;
    int lane = t & 31, wid = t >> 5;
    int base = t*4;
    int x0 = (base+0 < n) ? cnt[base+0] : 0;
    int x1 = (base+1 < n) ? cnt[base+1] : 0;
    int x2 = (base+2 < n) ? cnt[base+2] : 0;
    int x3 = (base+3 < n) ? cnt[base+3] : 0;
    int s = x0 + x1 + x2 + x3;
    int scan = s;
    #pragma unroll
    for (int o = 1; o < 32; o <<= 1){
        int y = __shfl_up_sync(0xffffffffu, scan, o);
        if (lane >= o) scan += y;
    }
    if (lane == 31) warpsum[wid] = scan;
    __syncthreads();
    if (wid == 0){
        int ws = warpsum[lane];
        #pragma unroll
        for (int o = 1; o < 32; o <<= 1){
            int y = __shfl_up_sync(0xffffffffu, ws, o);
            if (lane >= o) ws += y;
        }
        warpsum[lane] = ws;
    }
    __syncthreads();
    int excl = scan - s + (wid > 0 ? warpsum[wid-1] : 0);
    int run = excl;
    if (base+0 < n){ offs[base+0] = run; cur[base+0] = run; } run += x0;
    if (base+1 < n){ offs[base+1] = run; cur[base+1] = run; } run += x1;
    if (base+2 < n){ offs[base+2] = run; cur[base+2] = run; } run += x2;
    if (base+3 < n){ offs[base+3] = run; cur[base+3] = run; } run += x3;
    if (t == 1023) offs[n] = warpsum[31];
}
__global__ void k_exscan_all(const int* __restrict__ cnt,
                             int* o1,int* c1,int* o2,int* c2,
                             int* og0,int* cg0,int* og1,int* cg1,
                             int* og2,int* cg2,int* og3,int* cg3){
    switch (blockIdx.x){
        case 0: exscan_body(cnt,                 N1n, o1,  c1);  break;
        case 1: exscan_body(cnt+N1n,             N2n, o2,  c2);  break;
        case 2: exscan_body(cnt+N1n+N2n,         Pn,  og0, cg0); break;
        case 3: exscan_body(cnt+N1n+N2n+Pn,      Pn,  og1, cg1); break;
        case 4: exscan_body(cnt+N1n+N2n+2*Pn,    Mn,  og2, cg2); break;
        case 5: exscan_body(cnt+N1n+N2n+2*Pn+Mn, Mn,  og3, cg3); break;
    }
}

__global__ void k_scatter_all(const int* __restrict__ a1r, const int* __restrict__ a1c, const float* __restrict__ a1v,
                              const int* __restrict__ a2r, const int* __restrict__ a2c, const float* __restrict__ a2v,
                              const int* __restrict__ g0d, const int* __restrict__ g0s,
                              const int* __restrict__ g1d, const int* __restrict__ g1s,
                              const int* __restrict__ g2d, const int* __restrict__ g2s,
                              const int* __restrict__ g3d, const int* __restrict__ g3s,
                              int* cur1, int* scol1, float* sval1,
                              int* cur2, int* scol2, float* sval2,
                              int* curg0, int* ssrc0, int* curg1, int* ssrc1,
                              int* curg2, int* ssrc2, int* curg3, int* ssrc3){
    int i = blockIdx.x*blockDim.x + threadIdx.x;
    if (i >= ETOT) return;
    if (i < E1n){
        int pos = atomicAdd(&cur1[a1r[i]], 1);
        scol1[pos] = a1c[i]; sval1[pos] = a1v[i];
    } else if (i < E1n+E2n){
        int j = i-E1n;
        int pos = atomicAdd(&cur2[a2r[j]], 1);
        scol2[pos] = a2c[j]; sval2[pos] = a2v[j];
    } else if (i < E1n+E2n+EGPn){
        int j = i-E1n-E2n;
        int pos = atomicAdd(&curg0[g0d[j]], 1);
        ssrc0[pos] = g0s[j];
    } else if (i < E1n+E2n+2*EGPn){
        int j = i-E1n-E2n-EGPn;
        int pos = atomicAdd(&curg1[g1d[j]], 1);
        ssrc1[pos] = g1s[j];
    } else if (i < E1n+E2n+2*EGPn+EGMn){
        int j = i-E1n-E2n-2*EGPn;
        int pos = atomicAdd(&curg2[g2d[j]], 1);
        ssrc2[pos] = g2s[j];
    } else {
        int j = i-E1n-E2n-2*EGPn-EGMn;
        int pos = atomicAdd(&curg3[g3d[j]], 1);
        ssrc3[pos] = g3s[j];
    }
}

// fused init: lat1 = half(concat(pE,mE)), lat2 = half(concat(pE,dE)), accs = 0
__global__ void k_init_all(const float* __restrict__ pE, const float* __restrict__ mE,
                           const float* __restrict__ dE,
                           __half* __restrict__ lat1, float* __restrict__ acc1,
                           __half* __restrict__ lat2, float* __restrict__ acc2){
    int i = blockIdx.x*blockDim.x + threadIdx.x;
    if (i < N1n*Fn){
        float v = (i < Pn*Fn) ? pE[i] : mE[i - Pn*Fn];
        lat1[i] = __float2half_rn(v);
        acc1[i] = 0.f;
    } else if (i < (N1n+N2n)*Fn){
        int j = i - N1n*Fn;
        float v = (j < Pn*Fn) ? pE[j] : dE[j - Pn*Fn];
        lat2[j] = __float2half_rn(v);
        acc2[j] = 0.f;
    }
}

// ---------------- SpMM both graphs fused: warp per row ----------------
// layer2 (writeOut): also writes final acc rows for m_gcn / d_gcn straight to d_out
__global__ void k_spmm2(const int* __restrict__ offs1, const int* __restrict__ scol1, const float* __restrict__ sval1,
                        const __half* __restrict__ x1, __half* __restrict__ lo1, float* __restrict__ acc1,
                        const int* __restrict__ offs2, const int* __restrict__ scol2, const float* __restrict__ sval2,
                        const __half* __restrict__ x2, __half* __restrict__ lo2, float* __restrict__ acc2,
                        float* outM, float* outD){
    int gw = (blockIdx.x*blockDim.x + threadIdx.x) >> 5;
    int lane = threadIdx.x & 31;
    if (gw >= N1n + N2n) return;
    const int* offs; const int* scol; const float* sval; const __half* x;
    __half* lo; float* acc; int w; float* outp = nullptr;
    if (gw < N1n){
        offs = offs1; scol = scol1; sval = sval1; x = x1; lo = lo1; acc = acc1; w = gw;
        if (outM && w >= Pn) outp = outM + (size_t)(w - Pn) * Fn;
    } else {
        offs = offs2; scol = scol2; sval = sval2; x = x2; lo = lo2; acc = acc2; w = gw - N1n;
        if (outD && w >= Pn) outp = outD + (size_t)(w - Pn) * Fn;
    }
    int beg = offs[w], end = offs[w+1];
    float a0=0.f,a1=0.f,a2=0.f,a3=0.f,a4=0.f,a5=0.f,a6=0.f,a7=0.f;
    for (int base = beg; base < end; base += 32){
        int e = base + lane;
        int c = 0; float v = 0.f;
        if (e < end){ c = scol[e]; v = sval[e]; }
        int cnt = min(32, end - base);
        #pragma unroll 4
        for (int k = 0; k < cnt; k++){
            int cc = __shfl_sync(0xffffffffu, c, k);
            float vv = __shfl_sync(0xffffffffu, v, k);
            float4 raw = ((const float4*)(x + (size_t)cc * Fn))[lane];
            const __half2* hp = (const __half2*)&raw;
            float2 f0 = __half22float2(hp[0]);
            float2 f1 = __half22float2(hp[1]);
            float2 f2 = __half22float2(hp[2]);
            float2 f3 = __half22float2(hp[3]);
            a0 = fmaf(vv,f0.x,a0); a1 = fmaf(vv,f0.y,a1);
            a2 = fmaf(vv,f1.x,a2); a3 = fmaf(vv,f1.y,a3);
            a4 = fmaf(vv,f2.x,a4); a5 = fmaf(vv,f2.y,a5);
            a6 = fmaf(vv,f3.x,a6); a7 = fmaf(vv,f3.y,a7);
        }
    }
    a0 = a0>0.f?a0:0.5f*a0; a1 = a1>0.f?a1:0.5f*a1;
    a2 = a2>0.f?a2:0.5f*a2; a3 = a3>0.f?a3:0.5f*a3;
    a4 = a4>0.f?a4:0.5f*a4; a5 = a5>0.f?a5:0.5f*a5;
    a6 = a6>0.f?a6:0.5f*a6; a7 = a7>0.f?a7:0.5f*a7;
    float4 o;
    __half2* op = (__half2*)&o;
    op[0] = __floats2half2_rn(a0,a1);
    op[1] = __floats2half2_rn(a2,a3);
    op[2] = __floats2half2_rn(a4,a5);
    op[3] = __floats2half2_rn(a6,a7);
    ((float4*)(lo + (size_t)w * Fn))[lane] = o;
    float4* ac = (float4*)(acc + (size_t)w * Fn);
    float4 p0 = ac[2*lane];   p0.x+=a0; p0.y+=a1; p0.z+=a2; p0.w+=a3; ac[2*lane]   = p0;
    float4 p1 = ac[2*lane+1]; p1.x+=a4; p1.y+=a5; p1.z+=a6; p1.w+=a7; ac[2*lane+1] = p1;
    if (outp){
        ((float4*)outp)[2*lane]   = p0;
        ((float4*)outp)[2*lane+1] = p1;
    }
}

// ---------------- batched GEMM (4 GATs) with fused el/er epilogue ----------------
// feat[n,256] = A[n,256] @ W[256,256] (stored half); el/er per-head dots fused.
__global__ void k_gemm_elr(const float* __restrict__ acc1, const float* __restrict__ acc2,
                           const float* __restrict__ gatW, const float* __restrict__ gatAl,
                           const float* __restrict__ gatAr,
                           __half* __restrict__ feats, float* __restrict__ el, float* __restrict__ er){
    int gi = blockIdx.y;
    const float* A; int n, nodeoff;
    if (gi == 0){ A = acc1;                 n = Pn; nodeoff = GOFF0; }
    else if (gi == 1){ A = acc2;            n = Pn; nodeoff = GOFF1; }
    else if (gi == 2){ A = acc1 + (size_t)Pn*Fn; n = Mn; nodeoff = GOFF2; }
    else { A = acc1 + (size_t)Pn*Fn;        n = Mn; nodeoff = GOFF3; }
    int r0 = blockIdx.x * 16;
    if (r0 >= n) return;
    const float* W = gatW + (size_t)gi * Fn * Fn;

    __shared__ float sA[256][16];
    for (int i = threadIdx.x; i < 16*256; i += 256){
        int r = i >> 8, k = i & 255;
        sA[k][r] = (r0 + r < n) ? A[(size_t)(r0+r)*256 + k] : 0.f;
    }
    __syncthreads();
    int c = threadIdx.x;
    float acc[16];
    #pragma unroll
    for (int r = 0; r < 16; r++) acc[r] = 0.f;
    for (int k = 0; k < 256; k++){
        float wv = W[k*256 + c];
        const float4* s4 = (const float4*)sA[k];
        #pragma unroll
        for (int r4 = 0; r4 < 4; r4++){
            float4 av = s4[r4];
            acc[4*r4+0] = fmaf(av.x, wv, acc[4*r4+0]);
            acc[4*r4+1] = fmaf(av.y, wv, acc[4*r4+1]);
            acc[4*r4+2] = fmaf(av.z, wv, acc[4*r4+2]);
            acc[4*r4+3] = fmaf(av.w, wv, acc[4*r4+3]);
        }
    }
    // store half feats
    #pragma unroll
    for (int r = 0; r < 16; r++)
        if (r0 + r < n)
            feats[(size_t)(nodeoff + r0 + r)*256 + c] = __float2half_rn(acc[r]);

    // fused el/er: el[r,h] = sum_{c in head h} feat[r,c]*al[c]
    float alv = gatAl[gi*256 + c];
    float arv = gatAr[gi*256 + c];
    int lane = c & 31, wid = c >> 5;
    __shared__ float shl[16][8], shr[16][8];
    #pragma unroll
    for (int r = 0; r < 16; r++){
        float vl = acc[r]*alv;
        float vr = acc[r]*arv;
        #pragma unroll
        for (int o = 16; o >= 1; o >>= 1){
            vl += __shfl_xor_sync(0xffffffffu, vl, o);
            vr += __shfl_xor_sync(0xffffffffu, vr, o);
        }
        if (lane == 0){ shl[r][wid] = vl; shr[r][wid] = vr; }
    }
    __syncthreads();
    if (c < 64){
        int r = c >> 2, h = c & 3;
        if (r0 + r < n){
            el[(size_t)(nodeoff + r0 + r)*4 + h] = shl[r][2*h] + shl[r][2*h+1];
            er[(size_t)(nodeoff + r0 + r)*4 + h] = shr[r][2*h] + shr[r][2*h+1];
        }
    }
}

// ---------------- batched GAT: warp per dst node across all 4 graphs ----------------
__device__ __forceinline__ float lrelu2(float x){ return x > 0.f ? x : 0.2f*x; }

__global__ void k_gat_all(const int* __restrict__ offsg0, const int* __restrict__ ssrc0,
                          const int* __restrict__ offsg1, const int* __restrict__ ssrc1,
                          const int* __restrict__ offsg2, const int* __restrict__ ssrc2,
                          const int* __restrict__ offsg3, const int* __restrict__ ssrc3,
                          const float* __restrict__ el, const float* __restrict__ er,
                          const __half* __restrict__ feats, const float* __restrict__ gatB,
                          float* __restrict__ eall){
    int u = (blockIdx.x*blockDim.x + threadIdx.x) >> 5;
    int lane = threadIdx.x & 31;
    if (u >= NGAT) return;
    const int* offs; const int* ssrc; int w, gi, nodeoff;
    if (u < Pn){ offs = offsg0; ssrc = ssrc0; w = u; gi = 0; nodeoff = GOFF0; }
    else if (u < 2*Pn){ offs = offsg1; ssrc = ssrc1; w = u - Pn; gi = 1; nodeoff = GOFF1; }
    else if (u < 2*Pn + Mn){ offs = offsg2; ssrc = ssrc2; w = u - 2*Pn; gi = 2; nodeoff = GOFF2; }
    else { offs = offsg3; ssrc = ssrc3; w = u - 2*Pn - Mn; gi = 3; nodeoff = GOFF3; }
    int beg = offs[w], end = offs[w+1];
    float4 erv = *(const float4*)(er + (size_t)u*4);

    // pass 1: max
    float m0 = -1e30f, m1 = -1e30f, m2 = -1e30f, m3 = -1e30f;
    for (int e = beg + lane; e < end; e += 32){
        int s = ssrc[e];
        float4 elv = *(const float4*)(el + (size_t)(nodeoff + s)*4);
        m0 = fmaxf(m0, lrelu2(elv.x + erv.x));
        m1 = fmaxf(m1, lrelu2(elv.y + erv.y));
        m2 = fmaxf(m2, lrelu2(elv.z + erv.z));
        m3 = fmaxf(m3, lrelu2(elv.w + erv.w));
    }
    #pragma unroll
    for (int o = 16; o >= 1; o >>= 1){
        m0 = fmaxf(m0, __shfl_xor_sync(0xffffffffu, m0, o));
        m1 = fmaxf(m1, __shfl_xor_sync(0xffffffffu, m1, o));
        m2 = fmaxf(m2, __shfl_xor_sync(0xffffffffu, m2, o));
        m3 = fmaxf(m3, __shfl_xor_sync(0xffffffffu, m3, o));
    }
    // pass 2: sum of exp
    float s0 = 0.f, s1 = 0.f, s2 = 0.f, s3 = 0.f;
    for (int e = beg + lane; e < end; e += 32){
        int s = ssrc[e];
        float4 elv = *(const float4*)(el + (size_t)(nodeoff + s)*4);
        s0 += expf(lrelu2(elv.x + erv.x) - m0);
        s1 += expf(lrelu2(elv.y + erv.y) - m1);
        s2 += expf(lrelu2(elv.z + erv.z) - m2);
        s3 += expf(lrelu2(elv.w + erv.w) - m3);
    }
    #pragma unroll
    for (int o = 16; o >= 1; o >>= 1){
        s0 += __shfl_xor_sync(0xffffffffu, s0, o);
        s1 += __shfl_xor_sync(0xffffffffu, s1, o);
        s2 += __shfl_xor_sync(0xffffffffu, s2, o);
        s3 += __shfl_xor_sync(0xffffffffu, s3, o);
    }
    float d0 = 1.f/(s0 + 1e-9f), d1 = 1.f/(s1 + 1e-9f);
    float d2 = 1.f/(s2 + 1e-9f), d3 = 1.f/(s3 + 1e-9f);

    // pass 3: weighted aggregation (half feats, fp32 accum).
    // lane covers cols [8*lane, 8*lane+8) → head = lane>>3.
    int myh = lane >> 3;
    float a[8];
    #pragma unroll
    for (int i = 0; i < 8; i++) a[i] = 0.f;
    for (int base = beg; base < end; base += 32){
        int e = base + lane;
        int sidx = 0; float p0 = 0.f, p1 = 0.f, p2 = 0.f, p3 = 0.f;
        if (e < end){
            sidx = ssrc[e];
            float4 elv = *(const float4*)(el + (size_t)(nodeoff + sidx)*4);
            p0 = expf(lrelu2(elv.x + erv.x) - m0) * d0;
            p1 = expf(lrelu2(elv.y + erv.y) - m1) * d1;
            p2 = expf(lrelu2(elv.z + erv.z) - m2) * d2;
            p3 = expf(lrelu2(elv.w + erv.w) - m3) * d3;
        }
        int cnt = min(32, end - base);
        for (int k = 0; k < cnt; k++){
            int ss = __shfl_sync(0xffffffffu, sidx, k);
            float q0 = __shfl_sync(0xffffffffu, p0, k);
            float q1 = __shfl_sync(0xffffffffu, p1, k);
            float q2 = __shfl_sync(0xffffffffu, p2, k);
            float q3 = __shfl_sync(0xffffffffu, p3, k);
            float qq = (myh == 0) ? q0 : (myh == 1) ? q1 : (myh == 2) ? q2 : q3;
            float4 raw = ((const float4*)(feats + (size_t)(nodeoff + ss)*Fn))[lane];
            const __half2* hp = (const __half2*)&raw;
            float2 f0 = __half22float2(hp[0]);
            float2 f1 = __half22float2(hp[1]);
            float2 f2 = __half22float2(hp[2]);
            float2 f3 = __half22float2(hp[3]);
            a[0] = fmaf(qq,f0.x,a[0]); a[1] = fmaf(qq,f0.y,a[1]);
            a[2] = fmaf(qq,f1.x,a[2]); a[3] = fmaf(qq,f1.y,a[3]);
            a[4] = fmaf(qq,f2.x,a[4]); a[5] = fmaf(qq,f2.y,a[5]);
            a[6] = fmaf(qq,f3.x,a[6]); a[7] = fmaf(qq,f3.y,a[7]);
        }
    }
    // bias + ELU; lane stores cols [8*lane, 8*lane+8)
    const float* bias = gatB + gi*256;
    const float4* b4 = (const float4*)bias;
    float4 bb0 = b4[2*lane], bb1 = b4[2*lane+1];
    a[0] += bb0.x; a[1] += bb0.y; a[2] += bb0.z; a[3] += bb0.w;
    a[4] += bb1.x; a[5] += bb1.y; a[6] += bb1.z; a[7] += bb1.w;
    #pragma unroll
    for (int i = 0; i < 8; i++) a[i] = a[i] > 0.f ? a[i] : expm1f(a[i]);
    float4* o4 = (float4*)(eall + (size_t)u * Fn);
    o4[2*lane]   = make_float4(a[0],a[1],a[2],a[3]);
    o4[2*lane+1] = make_float4(a[4],a[5],a[6],a[7]);
}

// ---------------- semantic attention scores ----------------
__global__ void k_semscore(const float* __restrict__ eall,
                           const float* __restrict__ W1, const float* __restrict__ b1,
                           const float* __restrict__ W2, float* wsum){
    int zi = blockIdx.y;
    const float* z = eall + (size_t)((zi==0)?GOFF0:(zi==1)?GOFF1:(zi==2)?GOFF2:GOFF3)*Fn;
    int n = (zi < 2) ? Pn : Mn;
    int r0 = blockIdx.x * 16;
    if (r0 >= n) return;
    __shared__ float sZ[16][256];
    for (int i = threadIdx.x; i < 16*256; i += 128){
        int r = i >> 8, k = i & 255;
        sZ[r][k] = (r0 + r < n) ? z[(size_t)(r0+r)*256 + k] : 0.f;
    }
    __syncthreads();
    int c = threadIdx.x;
    float bc = b1[c];
    float acc[16];
    #pragma unroll
    for (int r = 0; r < 16; r++) acc[r] = bc;
    for (int k = 0; k < 256; k++){
        float w1v = W1[k*128 + c];
        #pragma unroll
        for (int r = 0; r < 16; r++)
            acc[r] = fmaf(sZ[r][k], w1v, acc[r]);
    }
    float w2 = W2[c];
    float local = 0.f;
    #pragma unroll
    for (int r = 0; r < 16; r++)
        if (r0 + r < n) local += tanhf(acc[r]) * w2;
    for (int o = 16; o >= 1; o >>= 1)
        local += __shfl_xor_sync(0xffffffffu, local, o);
    __shared__ float red[4];
    if ((threadIdx.x & 31) == 0) red[threadIdx.x >> 5] = local;
    __syncthreads();
    if (threadIdx.x == 0)
        atomicAdd(&wsum[zi], red[0] + red[1] + red[2] + red[3]);
}

// fused combine: patient (Pn*Fn elems) then med (Mn*Fn elems)
__global__ void k_combine2(const float* __restrict__ eall, const float* __restrict__ ws,
                           float* __restrict__ outPat, float* __restrict__ outMed){
    int i = blockIdx.x*blockDim.x + threadIdx.x;
    if (i < Pn*Fn){
        float w0 = ws[0]*(1.f/(float)Pn), w1 = ws[1]*(1.f/(float)Pn);
        float m = fmaxf(w0, w1);
        float x0 = expf(w0 - m), x1 = expf(w1 - m);
        float inv = 1.f/(x0 + x1);
        outPat[i] = (x0*inv)*eall[GOFF0*Fn + i] + (x1*inv)*eall[GOFF1*Fn + i];
    } else if (i < Pn*Fn + Mn*Fn){
        int j = i - Pn*Fn;
        float w0 = ws[2]*(1.f/(float)Mn), w1 = ws[3]*(1.f/(float)Mn);
        float m = fmaxf(w0, w1);
        float x0 = expf(w0 - m), x1 = expf(w1 - m);
        float inv = 1.f/(x0 + x1);
        outMed[j] = (x0*inv)*eall[GOFF2*Fn + j] + (x1*inv)*eall[GOFF3*Fn + j];
    }
}

// ---------------- final: t[j] = (sum_i relu(med_i)) . W_bot[:,j] ----------------
__global__ void k_medt(const float* __restrict__ med, const float* __restrict__ outW,
                       float* __restrict__ tvec){
    __shared__ float ms[256];
    int t = threadIdx.x;
    float s = 0.f;
    for (int i = 0; i < Mn; i++) s += fmaxf(med[i*256 + t], 0.f);
    ms[t] = s; __syncthreads();
    if (t < Mn){
        float acc = 0.f;
        for (int k = 0; k < 256; k++) acc = fmaf(ms[k], outW[(256 + k)*Mn + t], acc);
        tvec[t] = acc;
    }
}

// simi_pm[p,j] = M*( relu(patient[p]) . W_top[:,j] + b[j] ) + t[j]
__global__ void k_final(const float* __restrict__ patient, const float* __restrict__ outW,
                        const float* __restrict__ outb, const float* __restrict__ tvec,
                        float* __restrict__ simi){
    __shared__ float sA[256][8];
    int r0 = blockIdx.x * 8;
    for (int i = threadIdx.x; i < 8*256; i += blockDim.x){
        int r = i >> 8, k = i & 255;
        float v = (r0 + r < Pn) ? patient[(size_t)(r0+r)*256 + k] : 0.f;
        sA[k][r] = fmaxf(v, 0.f);
    }
    __syncthreads();
    int j = threadIdx.x;
    if (j < Mn){
        float acc[8];
        #pragma unroll
        for (int r = 0; r < 8; r++) acc[r] = 0.f;
        for (int k = 0; k < 256; k++){
            float wv = outW[k*Mn + j];
            const float4 a40 = *(const float4*)&sA[k][0];
            const float4 a41 = *(const float4*)&sA[k][4];
            acc[0] = fmaf(a40.x, wv, acc[0]); acc[1] = fmaf(a40.y, wv, acc[1]);
            acc[2] = fmaf(a40.z, wv, acc[2]); acc[3] = fmaf(a40.w, wv, acc[3]);
            acc[4] = fmaf(a41.x, wv, acc[4]); acc[5] = fmaf(a41.y, wv, acc[5]);
            acc[6] = fmaf(a41.z, wv, acc[6]); acc[7] = fmaf(a41.w, wv, acc[7]);
        }
        float tv = tvec[j], bb = outb[j];
        #pragma unroll
        for (int r = 0; r < 8; r++)
            if (r0 + r < Pn)
                simi[(size_t)(r0+r)*Mn + j] = (float)Mn * (acc[r] + bb) + tv;
    }
}

// ---------------- host launch ----------------
template <typename T>
static T* symaddr(const void* sym){
    void* p = nullptr;
    cudaGetSymbolAddress(&p, sym);
    return (T*)p;
}

extern "C" void kernel_launch(void* const* d_in, const int* in_sizes, int n_in,
                              void* d_out, int out_size){
    const int*   a1r = (const int*)  d_in[0];
    const int*   a1c = (const int*)  d_in[1];
    const float* a1v = (const float*)d_in[2];
    const int*   a2r = (const int*)  d_in[3];
    const int*   a2c = (const int*)  d_in[4];
    const float* a2v = (const float*)d_in[5];
    const int*   g0s = (const int*)  d_in[6];
    const int*   g0d = (const int*)  d_in[7];
    const int*   g1s = (const int*)  d_in[8];
    const int*   g1d = (const int*)  d_in[9];
    const int*   g2s = (const int*)  d_in[10];
    const int*   g2d = (const int*)  d_in[11];
    const int*   g3s = (const int*)  d_in[12];
    const int*   g3d = (const int*)  d_in[13];
    int kr = (n_in >= 27) ? 1 : 0;
    const float* pE    = (const float*)d_in[14 + kr];
    const float* mE    = (const float*)d_in[15 + kr];
    const float* dE    = (const float*)d_in[16 + kr];
    const float* gatW  = (const float*)d_in[17 + kr];
    const float* gatAl = (const float*)d_in[18 + kr];
    const float* gatAr = (const float*)d_in[19 + kr];
    const float* gatB  = (const float*)d_in[20 + kr];
    const float* saW1  = (const float*)d_in[21 + kr];
    const float* saB1  = (const float*)d_in[22 + kr];
    const float* saW2  = (const float*)d_in[23 + kr];
    const float* outW  = (const float*)d_in[24 + kr];
    const float* outB  = (const float*)d_in[25 + kr];
    float* out = (float*)d_out;

    __half* hlat1a = symaddr<__half>(g_hlat1a); __half* hlat1b = symaddr<__half>(g_hlat1b);
    __half* hlat2a = symaddr<__half>(g_hlat2a); __half* hlat2b = symaddr<__half>(g_hlat2b);
    float* acc1  = symaddr<float>(g_acc1);
    float* acc2  = symaddr<float>(g_acc2);
    int* cnt   = symaddr<int>(g_cnt);
    int* offs1 = symaddr<int>(g_offs1); int* cur1 = symaddr<int>(g_cur1);
    int* offs2 = symaddr<int>(g_offs2); int* cur2 = symaddr<int>(g_cur2);
    int* scol1 = symaddr<int>(g_scol1); float* sval1 = symaddr<float>(g_sval1);
    int* scol2 = symaddr<int>(g_scol2); float* sval2 = symaddr<float>(g_sval2);
    int* offsg0 = symaddr<int>(g_offsg0); int* curg0 = symaddr<int>(g_curg0); int* ssrc0 = symaddr<int>(g_ssrc0);
    int* offsg1 = symaddr<int>(g_offsg1); int* curg1 = symaddr<int>(g_curg1); int* ssrc1 = symaddr<int>(g_ssrc1);
    int* offsg2 = symaddr<int>(g_offsg2); int* curg2 = symaddr<int>(g_curg2); int* ssrc2 = symaddr<int>(g_ssrc2);
    int* offsg3 = symaddr<int>(g_offsg3); int* curg3 = symaddr<int>(g_curg3); int* ssrc3 = symaddr<int>(g_ssrc3);
    __half* feats = symaddr<__half>(g_feats);
    float* el = symaddr<float>(g_el); float* er = symaddr<float>(g_er);
    float* eall = symaddr<float>(g_eall);
    float* wsum = symaddr<float>(g_wsum);
    float* tvec = symaddr<float>(g_tvec);

    const int B = 256;

    // ---- fused CSR builds ----
    k_zero_all<<<(CNT_TOT+B-1)/B, B>>>(cnt, wsum);
    k_hist_all<<<(ETOT+B-1)/B, B>>>(a1r, a2r, g0d, g1d, g2d, g3d, cnt);
    k_exscan_all<<<6, 1024>>>(cnt, offs1, cur1, offs2, cur2,
                              offsg0, curg0, offsg1, curg1,
                              offsg2, curg2, offsg3, curg3);
    k_scatter_all<<<(ETOT+B-1)/B, B>>>(a1r, a1c, a1v, a2r, a2c, a2v,
                                       g0d, g0s, g1d, g1s, g2d, g2s, g3d, g3s,
                                       cur1, scol1, sval1, cur2, scol2, sval2,
                                       curg0, ssrc0, curg1, ssrc1,
                                       curg2, ssrc2, curg3, ssrc3);

    // ---- init embeds (half) + zero accs (one launch) ----
    k_init_all<<<((N1n+N2n)*Fn+B-1)/B, B>>>(pE, mE, dE, hlat1a, acc1, hlat2a, acc2);

    // ---- 2 GNN layers, both graphs fused per layer ----
    int spmmBlocks = (N1n + N2n + 7)/8;
    k_spmm2<<<spmmBlocks, B>>>(offs1, scol1, sval1, hlat1a, hlat1b, acc1,
                               offs2, scol2, sval2, hlat2a, hlat2b, acc2,
                               nullptr, nullptr);
    k_spmm2<<<spmmBlocks, B>>>(offs1, scol1, sval1, hlat1b, hlat1a, acc1,
                               offs2, scol2, sval2, hlat2b, hlat2a, acc2,
                               out + OUT_MGCN, out + OUT_DGCN);

    // ---- batched GEMM + fused el/er ----
    {
        dim3 grid((Pn+15)/16, 4);
        k_gemm_elr<<<grid, 256>>>(acc1, acc2, gatW, gatAl, gatAr, feats, el, er);
    }

    // ---- batched GAT aggregate (all 4300 nodes) ----
    k_gat_all<<<(NGAT+7)/8, B>>>(offsg0, ssrc0, offsg1, ssrc1, offsg2, ssrc2, offsg3, ssrc3,
                                 el, er, feats, gatB, eall);

    // ---- semantic attention ----
    {
        dim3 grid((Pn+15)/16, 4);
        k_semscore<<<grid, 128>>>(eall, saW1, saB1, saW2, wsum);
    }
    k_combine2<<<((Pn+Mn)*Fn+B-1)/B, B>>>(eall, wsum, out + OUT_PAT, out + OUT_MED);

    // ---- final similarity (algebraically collapsed) ----
    k_medt<<<1, 256>>>(out + OUT_MED, outW, tvec);
    k_final<<<(Pn+7)/8, 160>>>(out + OUT_PAT, outW, outB, tvec, out + OUT_SIMI);
}